// round 10
// baseline (speedup 1.0000x reference)
#include <cuda_runtime.h>
#include <cuda_bf16.h>
#include <math.h>
#include <stdint.h>

#define NPTS 8192
#define CCH  128
#define KSEL 128
#define KNN  32
#define KCAND 192      // approximate preselection size (slack 64 over KSEL)
#define CAND_CAP 768

// ---------------- scratch (device globals; no allocation) ----------------
__device__ __nv_bfloat16 g_corrh[(size_t)NPTS * NPTS]; // 128 MB approx corr
__device__ __nv_bfloat16 g_f1hi[(size_t)NPTS * CCH];   // [n][k] bf16
__device__ __nv_bfloat16 g_f2hi[(size_t)NPTS * CCH];
__device__ float  g_f1t[(size_t)NPTS * CCH];           // [n][k] fp32 (exact re-rank)
__device__ float  g_f2t[(size_t)NPTS * CCH];
__device__ unsigned g_cand[(size_t)NPTS * CAND_CAP];
__device__ unsigned g_ccnt[NPTS];
__device__ float  g_tcorr[NPTS * KSEL];
__device__ float  g_txyz[NPTS * KSEL * 3];
__device__ float  g_vfeat[108 * NPTS];
__device__ float  g_vcorr[NPTS * 27];
__device__ float  g_vxyz[NPTS * 27 * 3];
__device__ float  g_kin[NPTS * KNN * 4];
__device__ float  g_hout[128 * NPTS];

__device__ double g_vox_sum[8],  g_vox_sum2[8];
__device__ double g_knn_sum[8],  g_knn_sum2[8];
__device__ double g_out_sum[8],  g_out_sum2[8];
__device__ float  g_vox_mu[8], g_vox_inv[8];
__device__ float  g_knn_mu[8], g_knn_inv[8];
__device__ float  g_out_mu[8], g_out_inv[8];

// ---------------- helpers ----------------
__device__ __forceinline__ unsigned f2ord(float f) {
    unsigned u = __float_as_uint(f);
    return (u & 0x80000000u) ? ~u : (u | 0x80000000u);
}
__device__ __forceinline__ uint32_t smem_u32(const void* p) {
    uint32_t a;
    asm("{ .reg .u64 t; cvta.to.shared.u64 t, %1; cvt.u32.u64 %0, t; }" : "=r"(a) : "l"(p));
    return a;
}

// ---------------- Kp: transpose; write fp32 [n][k] + bf16 hi [n][k]; zero stats --
__global__ __launch_bounds__(256) void prep_kernel(const float* __restrict__ f1,
                                                   const float* __restrict__ f2) {
    __shared__ float tile[128][65];
    if (blockIdx.x == 0 && blockIdx.y == 0 && threadIdx.x < 8) {
        int q = threadIdx.x;
        g_vox_sum[q] = 0.0; g_vox_sum2[q] = 0.0;
        g_knn_sum[q] = 0.0; g_knn_sum2[q] = 0.0;
        g_out_sum[q] = 0.0; g_out_sum2[q] = 0.0;
    }
    const float* src = blockIdx.y ? f2 : f1;
    __nv_bfloat16* dhi = blockIdx.y ? g_f2hi : g_f1hi;
    float* dt = blockIdx.y ? g_f2t : g_f1t;
    int n0 = blockIdx.x * 64;
    int t = threadIdx.x;
    for (int i = t; i < 128 * 64; i += 256) {
        int n = i & 63;
        int k = i >> 6;
        tile[k][n] = src[(size_t)k * NPTS + n0 + n];
    }
    __syncthreads();
    for (int i = t; i < 64 * 128; i += 256) {
        int k = i & 127;
        int n = i >> 7;
        float v = tile[k][n];
        dt[(size_t)(n0 + n) * CCH + k]  = v;
        dhi[(size_t)(n0 + n) * CCH + k] = __float2bfloat16(v);
    }
}

// ---------------- K1: bf16 GEMM via mma.sync (HMMA), 128x128 per CTA, bf16 out --
#define TILE_BYTES 32768
#define SM_AHI 0
#define SM_BHI (SM_AHI + TILE_BYTES)
#define SM_GEMM_TOTAL (2 * TILE_BYTES)
#define SOUT 136   // bf16 elements per staged output row (272 B)

__device__ __forceinline__ uint32_t swz_off(int row, int chunk) {
    return (uint32_t)(row * 256 + ((chunk ^ (row & 7)) << 4));
}

__global__ __launch_bounds__(256) void gemm_mma_kernel() {
    extern __shared__ char smem[];
    uint32_t sbase = smem_u32(smem);
    int t = threadIdx.x;        // 256
    int bm = blockIdx.y * 128;
    int bn = blockIdx.x * 128;

#pragma unroll 1
    for (int tl = 0; tl < 2; tl++) {
        const __nv_bfloat16* sp = tl ? g_f2hi : g_f1hi;
        int srow = tl ? bn : bm;
        int soff = tl ? SM_BHI : SM_AHI;
        const uint4* src = (const uint4*)(sp + (size_t)srow * CCH);
#pragma unroll
        for (int it = 0; it < 8; it++) {
            int i   = t + it * 256;     // 0..2047
            int row = i >> 4;
            int chk = i & 15;
            uint4 v = src[(size_t)row * 16 + chk];
            *(uint4*)(smem + soff + swz_off(row, chk)) = v;
        }
    }
    __syncthreads();

    int wid  = t >> 5;
    int lane = t & 31;
    int wm = wid & 3;
    int wn = wid >> 2;
    int lrow = lane & 7;
    int lblk = lane >> 3;

    float acc[2][8][4];
#pragma unroll
    for (int i = 0; i < 2; i++)
#pragma unroll
        for (int j = 0; j < 8; j++)
#pragma unroll
            for (int q = 0; q < 4; q++) acc[i][j][q] = 0.f;

    uint32_t abase = sbase + SM_AHI;
    uint32_t bbase = sbase + SM_BHI;
#pragma unroll 1
    for (int ks = 0; ks < 8; ks++) {
        uint32_t a[2][4];
#pragma unroll
        for (int i = 0; i < 2; i++) {
            int row = wm * 32 + i * 16 + lrow + (lblk & 1) * 8;
            int chk = ks * 2 + (lblk >> 1);
            uint32_t addr = abase + swz_off(row, chk);
            asm volatile("ldmatrix.sync.aligned.m8n8.x4.shared.b16 {%0,%1,%2,%3}, [%4];"
                         : "=r"(a[i][0]), "=r"(a[i][1]), "=r"(a[i][2]), "=r"(a[i][3])
                         : "r"(addr));
        }
        uint32_t b[8][2];
#pragma unroll
        for (int jj = 0; jj < 4; jj++) {
            int row = wn * 64 + (jj * 2 + (lblk >> 1)) * 8 + lrow;
            int chk = ks * 2 + (lblk & 1);
            uint32_t addr = bbase + swz_off(row, chk);
            uint32_t r0, r1, r2, r3;
            asm volatile("ldmatrix.sync.aligned.m8n8.x4.shared.b16 {%0,%1,%2,%3}, [%4];"
                         : "=r"(r0), "=r"(r1), "=r"(r2), "=r"(r3)
                         : "r"(addr));
            b[jj * 2][0] = r0; b[jj * 2][1] = r1;
            b[jj * 2 + 1][0] = r2; b[jj * 2 + 1][1] = r3;
        }
#pragma unroll
        for (int i = 0; i < 2; i++)
#pragma unroll
            for (int j = 0; j < 8; j++) {
                asm volatile(
                    "mma.sync.aligned.m16n8k16.row.col.f32.bf16.bf16.f32 "
                    "{%0,%1,%2,%3}, {%4,%5,%6,%7}, {%8,%9}, {%0,%1,%2,%3};"
                    : "+f"(acc[i][j][0]), "+f"(acc[i][j][1]),
                      "+f"(acc[i][j][2]), "+f"(acc[i][j][3])
                    : "r"(a[i][0]), "r"(a[i][1]), "r"(a[i][2]), "r"(a[i][3]),
                      "r"(b[j][0]), "r"(b[j][1]));
            }
    }

    // ---- epilogue: stage into smem, then coalesced 256B rows ----
    __syncthreads();
    __nv_bfloat16* stile = (__nv_bfloat16*)smem;
    const float scale = 0.088388347648318447f;  // 1/sqrt(128)
#pragma unroll
    for (int i = 0; i < 2; i++) {
        int row0 = wm * 32 + i * 16 + (lane >> 2);
#pragma unroll
        for (int j = 0; j < 8; j++) {
            int col = wn * 64 + j * 8 + ((lane & 3) << 1);
            float2 v0, v1;
            v0.x = acc[i][j][0] * scale; v0.y = acc[i][j][1] * scale;
            v1.x = acc[i][j][2] * scale; v1.y = acc[i][j][3] * scale;
            *(__nv_bfloat162*)&stile[row0 * SOUT + col]       = __float22bfloat162_rn(v0);
            *(__nv_bfloat162*)&stile[(row0 + 8) * SOUT + col] = __float22bfloat162_rn(v1);
        }
    }
    __syncthreads();
#pragma unroll
    for (int it = 0; it < 8; it++) {
        int idx = t + it * 256;     // 0..2047
        int row = idx >> 4;
        int seg = idx & 15;
        uint4 v = *(const uint4*)&stile[row * SOUT + seg * 8];
        *(uint4*)&g_corrh[(size_t)(bm + row) * NPTS + bn + seg * 8] = v;
    }
}

// ---------------- K2a: top-KCAND preselect (12-bit radix, one pass) -------------
__global__ __launch_bounds__(256) void topk_select_kernel() {
    __shared__ unsigned s_key2[NPTS / 2];        // 16 KB packed ord16 pairs
    __shared__ unsigned s_hist[4096];            // 16 KB (12-bit bins)
    __shared__ unsigned s_gsum[256];             // 1 KB (group = 16 bins)
    __shared__ unsigned s_crossg, s_cumabove, s_thr, s_ccnt;

    int n = blockIdx.x;
    int t = threadIdx.x;  // 256

    for (int i = t; i < 4096; i += 256) s_hist[i] = 0;
    if (t == 0) s_ccnt = 0;
    __syncthreads();

    // pass A: load bf16 row, SIMD ord16 (both halves at once), 12-bit hist
    const uint4* rowp = (const uint4*)(g_corrh + (size_t)n * NPTS);
    for (int i = t; i < NPTS / 8; i += 256) {
        uint4 v = rowp[i];
        unsigned w[4] = {v.x, v.y, v.z, v.w};
#pragma unroll
        for (int q = 0; q < 4; q++) {
            unsigned vv = w[q];
            unsigned mask = (((vv >> 15) & 0x00010001u) * 0x7FFFu) | 0x80008000u;
            unsigned key2 = vv ^ mask;
            s_key2[i * 4 + q] = key2;
            atomicAdd(&s_hist[(key2 >> 4) & 0xFFFu], 1u);
            atomicAdd(&s_hist[key2 >> 20], 1u);
        }
    }
    __syncthreads();
    // group sums (16 bins each)
    {
        unsigned sum = 0;
#pragma unroll
        for (int b = 0; b < 16; b++) sum += s_hist[t * 16 + b];
        s_gsum[t] = sum;
    }
    __syncthreads();
    // warp 0: find crossing group via suffix scan (descending key order)
    if (t < 32) {
        int lane = t;
        int gtop = 255 - lane * 8;   // lane 0 owns the TOP 8 groups
        unsigned local = 0;
#pragma unroll
        for (int q = 0; q < 8; q++) local += s_gsum[gtop - q];
        unsigned pre = local;
#pragma unroll
        for (int d = 1; d < 32; d <<= 1) {
            unsigned other = __shfl_up_sync(0xFFFFFFFFu, pre, d);
            if (lane >= d) pre += other;
        }
        unsigned run = pre - local;  // count strictly above this lane's block
#pragma unroll
        for (int q = 0; q < 8; q++) {
            int g = gtop - q;
            unsigned c = s_gsum[g];
            if (run < KCAND && run + c >= KCAND) { s_crossg = (unsigned)g; s_cumabove = run; }
            run += c;
        }
    }
    __syncthreads();
    if (t == 0) {
        unsigned g = s_crossg;
        unsigned cum = s_cumabove;
        unsigned thr = g * 16;
        for (int b = 15; b >= 0; b--) {
            unsigned h = s_hist[g * 16 + b];
            if (cum + h >= KCAND) { thr = g * 16 + (unsigned)b; break; }
            cum += h;
        }
        s_thr = thr << 4;
    }
    __syncthreads();
    unsigned thr = s_thr;
    // pass C: compact candidate indices (key >= thr), 2 keys per LDS
    for (int i = t; i < NPTS / 2; i += 256) {
        unsigned kk = s_key2[i];
        if ((kk & 0xFFFFu) >= thr) {
            unsigned ci = atomicAdd(&s_ccnt, 1u);
            if (ci < CAND_CAP) g_cand[(size_t)n * CAND_CAP + ci] = (unsigned)(i * 2);
        }
        if ((kk >> 16) >= thr) {
            unsigned ci = atomicAdd(&s_ccnt, 1u);
            if (ci < CAND_CAP) g_cand[(size_t)n * CAND_CAP + ci] = (unsigned)(i * 2 + 1);
        }
    }
    __syncthreads();
    if (t == 0) g_ccnt[n] = min(s_ccnt, (unsigned)CAND_CAP);
}

// ---------------- K2b: exact fp32 dots + rank over candidates -> top-128 --------
__global__ __launch_bounds__(256) void topk_rerank_kernel(const float* __restrict__ xyz2) {
    __shared__ float    s_f1[CCH];
    __shared__ unsigned s_cidx[CAND_CAP];
    __shared__ float    s_val[CAND_CAP];

    int n = blockIdx.x;
    int t = threadIdx.x;  // 256
    unsigned C = g_ccnt[n];

    if (t < 128) s_f1[t] = g_f1t[(size_t)n * CCH + t];
    for (unsigned c = t; c < C; c += 256) s_cidx[c] = g_cand[(size_t)n * CAND_CAP + c];
    __syncthreads();

    const float scale = 0.088388347648318447f;
    for (unsigned c = t; c < C; c += 256) {
        unsigned m = s_cidx[c];
        const float4* f2 = (const float4*)(g_f2t + (size_t)m * CCH);
        const float4* f1 = (const float4*)s_f1;
        float acc = 0.f;
#pragma unroll 4
        for (int k = 0; k < CCH / 4; k++) {
            float4 a = f1[k];
            float4 b = f2[k];
            acc += a.x * b.x;
            acc += a.y * b.y;
            acc += a.z * b.z;
            acc += a.w * b.w;
        }
        s_val[c] = acc * scale;
    }
    __syncthreads();

    for (unsigned c = t; c < C; c += 256) {
        float vc = s_val[c];
        unsigned mc = s_cidx[c];
        unsigned r = 0;
        for (unsigned j = 0; j < C; j++) {
            float vj = s_val[j];
            r += (vj > vc || (vj == vc && s_cidx[j] < mc)) ? 1u : 0u;
        }
        if (r < KSEL) {
            g_tcorr[(size_t)n * KSEL + r] = vc;
            size_t o = ((size_t)n * KSEL + r) * 3;
            g_txyz[o + 0] = xyz2[(size_t)mc * 3 + 0];
            g_txyz[o + 1] = xyz2[(size_t)mc * 3 + 1];
            g_txyz[o + 2] = xyz2[(size_t)mc * 3 + 2];
        }
    }
}

// ---------------- K3: per-point voxel levels + coarse stage + knn select + GN stats
__global__ __launch_bounds__(128) void pointfeat_kernel(const float* __restrict__ coords,
                                 const float* __restrict__ vw1, const float* __restrict__ vb1,
                                 const float* __restrict__ kw1, const float* __restrict__ kb1) {
    __shared__ float s_c[KSEL];
    __shared__ float s_x[KSEL][3];
    __shared__ float s_dd[KSEL];
    __shared__ float s_coord[3];
    __shared__ float s_add[27], s_cnt[27];
    __shared__ unsigned long long s_center[28];
    __shared__ float s_mv[27][3];
    __shared__ int   s_oob[27];
    __shared__ float s_cadd[28], s_ccnt[28];
    __shared__ float s_vcorr[27];
    __shared__ float s_kin[KNN][4];
    __shared__ float s_gs[8], s_gs2[8], s_kgs[8], s_kgs2[8];
    __shared__ unsigned long long s_top1key;

    int n = blockIdx.x;
    int t = threadIdx.x;  // 128

    s_c[t] = g_tcorr[(size_t)n * KSEL + t];
    {
        size_t o = ((size_t)n * KSEL + t) * 3;
        s_x[t][0] = g_txyz[o + 0];
        s_x[t][1] = g_txyz[o + 1];
        s_x[t][2] = g_txyz[o + 2];
    }
    if (t < 3) s_coord[t] = coords[(size_t)n * 3 + t];
    if (t == 0) s_top1key = 0ull;
    __syncthreads();
    float c0 = s_coord[0], c1 = s_coord[1], c2 = s_coord[2];
    float x0 = s_x[t][0], x1 = s_x[t][1], x2 = s_x[t][2];

    {
        float dx = x0 - c0, dy = x1 - c1, dz = x2 - c2;
        s_dd[t] = dx * dx + dy * dy + dz * dz;
        unsigned long long key =
            ((unsigned long long)f2ord(s_c[t]) << 32) | (unsigned)(127 - t);
        atomicMax(&s_top1key, key);
    }

    for (int lev = 0; lev < 3; lev++) {
        if (t < 27) { s_add[t] = 0.f; s_cnt[t] = 0.f; }
        __syncthreads();
        float r  = 0.25f * (float)(1 << lev);
        float d0 = rintf((x0 - c0) / r);
        float d1 = rintf((x1 - c1) / r);
        float d2 = rintf((x2 - c2) / r);
        if (fabsf(d0) <= 1.0f && fabsf(d1) <= 1.0f && fabsf(d2) <= 1.0f) {
            int cube = (int)((d0 + 1.f) * 9.f + (d1 + 1.f) * 3.f + (d2 + 1.f));
            atomicAdd(&s_add[cube], s_c[t]);
            atomicAdd(&s_cnt[cube], 1.f);
        }
        __syncthreads();
        if (t < 27)
            g_vfeat[(size_t)(lev * 27 + t) * NPTS + n] = s_add[t] / fmaxf(s_cnt[t], 1.f);
        __syncthreads();
    }

    if (t < 28) s_center[t] = 0ull;
    __syncthreads();
    {
        float d0 = rintf((x0 - c0) / 4.0f);
        float d1 = rintf((x1 - c1) / 4.0f);
        float d2 = rintf((x2 - c2) / 4.0f);
        if (fabsf(d0) <= 1.5f && fabsf(d1) <= 1.5f && fabsf(d2) <= 1.5f) {
            int b = (int)((d0 + 1.f) * 9.f + (d1 + 1.f) * 3.f + (d2 + 1.f)) + 1;
            unsigned long long key =
                ((unsigned long long)f2ord(s_c[t]) << 32) | (unsigned)(127 - t);
            atomicMax(&s_center[b], key);
        }
    }
    __syncthreads();
    int top1 = 127 - (int)(s_top1key & 0xFFFFFFFFu);
    if (t < 27) {
        unsigned long long k = s_center[t + 1];
        int oob, idx;
        if (k == 0ull) { oob = 1; idx = top1; }
        else {
            float v = __uint_as_float(((unsigned)(k >> 32) & 0x80000000u)
                        ? ((unsigned)(k >> 32) & 0x7FFFFFFFu)
                        : ~(unsigned)(k >> 32));
            oob = (v <= 0.f);
            idx = oob ? top1 : (127 - (int)(k & 0xFFFFFFFFu));
        }
        s_oob[t] = oob;
        float cc0 = s_x[idx][0], cc1 = s_x[idx][1], cc2 = s_x[idx][2];
        float bx = (float)((t / 9) % 3 - 1);
        float by = (float)((t / 3) % 3 - 1);
        float bz = (float)(t % 3 - 1);
        float vk0 = c0 + bx * 4.f, vk1 = c1 + by * 4.f, vk2 = c2 + bz * 4.f;
        float m0 = fminf(fmaxf(cc0 - vk0, -1.f), 1.f) + vk0;
        float m1 = fminf(fmaxf(cc1 - vk1, -1.f), 1.f) + vk1;
        float m2 = fminf(fmaxf(cc2 - vk2, -1.f), 1.f) + vk2;
        s_mv[t][0] = m0; s_mv[t][1] = m1; s_mv[t][2] = m2;
        size_t o = ((size_t)n * 27 + t) * 3;
        g_vxyz[o + 0] = m0; g_vxyz[o + 1] = m1; g_vxyz[o + 2] = m2;
    }
    if (t < 28) { s_cadd[t] = 0.f; s_ccnt[t] = 0.f; }
    __syncthreads();

    {
        int idx = 27;
        for (int k = 0; k < 27; k++) {
            if (!s_oob[k]) {
                if (fabsf((x0 - s_mv[k][0]) / 2.0f) <= 0.5f &&
                    fabsf((x1 - s_mv[k][1]) / 2.0f) <= 0.5f &&
                    fabsf((x2 - s_mv[k][2]) / 2.0f) <= 0.5f)
                    idx = k;
            }
        }
        atomicAdd(&s_cadd[idx], s_c[t]);
        atomicAdd(&s_ccnt[idx], 1.f);
    }
    {
        float dd = s_dd[t];
        int r = 0;
#pragma unroll 8
        for (int j = 0; j < KSEL; j++) {
            float dj = s_dd[j];
            r += (dj < dd || (dj == dd && j < t)) ? 1 : 0;
        }
        if (r < KNN) {
            float kc = s_c[t];
            float k0 = x0 - c0, k1 = x1 - c1, k2 = x2 - c2;
            s_kin[r][0] = kc; s_kin[r][1] = k0; s_kin[r][2] = k1; s_kin[r][3] = k2;
            size_t o = ((size_t)n * KNN + r) * 4;
            g_kin[o] = kc; g_kin[o + 1] = k0; g_kin[o + 2] = k1; g_kin[o + 3] = k2;
        }
    }
    __syncthreads();
    if (t < 27) {
        float vc = s_cadd[t] / fmaxf(s_ccnt[t], 1.f);
        s_vcorr[t] = vc;
        g_vcorr[(size_t)n * 27 + t] = vc;
    }
    __syncthreads();

    if (t >= 64 && t < 96) {
        int ch = t - 64;
        float w0 = vw1[ch * 4 + 0], w1_ = vw1[ch * 4 + 1];
        float w2_ = vw1[ch * 4 + 2], w3_ = vw1[ch * 4 + 3];
        float bb = vb1[ch];
        float sum = 0.f, sum2 = 0.f;
#pragma unroll
        for (int k = 0; k < 27; k++) {
            float h = w0 * s_vcorr[k] + w1_ * s_mv[k][0] + w2_ * s_mv[k][1] + w3_ * s_mv[k][2] + bb;
            sum += h; sum2 += h * h;
        }
        sum  += __shfl_xor_sync(0xFFFFFFFFu, sum, 1);
        sum2 += __shfl_xor_sync(0xFFFFFFFFu, sum2, 1);
        sum  += __shfl_xor_sync(0xFFFFFFFFu, sum, 2);
        sum2 += __shfl_xor_sync(0xFFFFFFFFu, sum2, 2);
        if ((ch & 3) == 0) { s_gs[ch >> 2] = sum; s_gs2[ch >> 2] = sum2; }
    }
    if (t < 64) {
        int ch = t;
        float w0 = kw1[ch * 4 + 0], w1_ = kw1[ch * 4 + 1];
        float w2_ = kw1[ch * 4 + 2], w3_ = kw1[ch * 4 + 3];
        float bb = kb1[ch];
        float sum = 0.f, sum2 = 0.f;
#pragma unroll
        for (int s = 0; s < KNN; s++) {
            float h = w0 * s_kin[s][0] + w1_ * s_kin[s][1] + w2_ * s_kin[s][2] + w3_ * s_kin[s][3] + bb;
            sum += h; sum2 += h * h;
        }
        sum  += __shfl_xor_sync(0xFFFFFFFFu, sum, 1);
        sum2 += __shfl_xor_sync(0xFFFFFFFFu, sum2, 1);
        sum  += __shfl_xor_sync(0xFFFFFFFFu, sum, 2);
        sum2 += __shfl_xor_sync(0xFFFFFFFFu, sum2, 2);
        sum  += __shfl_xor_sync(0xFFFFFFFFu, sum, 4);
        sum2 += __shfl_xor_sync(0xFFFFFFFFu, sum2, 4);
        if ((ch & 7) == 0) { s_kgs[ch >> 3] = sum; s_kgs2[ch >> 3] = sum2; }
    }
    __syncthreads();
    if (t < 8) {
        atomicAdd(&g_vox_sum[t],  (double)s_gs[t]);
        atomicAdd(&g_vox_sum2[t], (double)s_gs2[t]);
        atomicAdd(&g_knn_sum[t],  (double)s_kgs[t]);
        atomicAdd(&g_knn_sum2[t], (double)s_kgs2[t]);
    }
}

// ---------------- K4: finalize vox + knn GN stats ----------------
__global__ void finalize_vk_kernel() {
    int t = threadIdx.x;
    if (t < 8) {
        double cnt = 4.0 * NPTS * 27.0;
        double mu  = g_vox_sum[t] / cnt;
        double var = g_vox_sum2[t] / cnt - mu * mu;
        g_vox_mu[t]  = (float)mu;
        g_vox_inv[t] = (float)(1.0 / sqrt(var + 1e-5));
    } else if (t < 16) {
        int g = t - 8;
        double cnt = 8.0 * NPTS * (double)KNN;
        double mu  = g_knn_sum[g] / cnt;
        double var = g_knn_sum2[g] / cnt - mu * mu;
        g_knn_mu[g]  = (float)mu;
        g_knn_inv[g] = (float)(1.0 / sqrt(var + 1e-5));
    }
}

// ---------------- K5: vox MLP apply -> vfeat channels 81..107 ----------------
__global__ void vox_apply_kernel(const float* __restrict__ w1, const float* __restrict__ b1,
                                 const float* __restrict__ gma, const float* __restrict__ bta,
                                 const float* __restrict__ pr, const float* __restrict__ w2,
                                 const float* __restrict__ b2) {
    int idx = blockIdx.x * blockDim.x + threadIdx.x;
    if (idx >= NPTS * 27) return;
    int n = idx / 27, k = idx % 27;
    float vc = g_vcorr[idx];
    float m0 = g_vxyz[(size_t)idx * 3 + 0];
    float m1 = g_vxyz[(size_t)idx * 3 + 1];
    float m2 = g_vxyz[(size_t)idx * 3 + 2];
    float a = pr[0];
    float acc = b2[0];
#pragma unroll
    for (int ch = 0; ch < 32; ch++) {
        float h = w1[ch * 4 + 0] * vc + w1[ch * 4 + 1] * m0
                + w1[ch * 4 + 2] * m1 + w1[ch * 4 + 3] * m2 + b1[ch];
        int gr = ch >> 2;
        h = (h - g_vox_mu[gr]) * g_vox_inv[gr] * gma[ch] + bta[ch];
        h = (h >= 0.f) ? h : a * h;
        acc += w2[ch] * h;
    }
    g_vfeat[(size_t)(81 + k) * NPTS + n] = acc;
}

// ---------------- K6: out conv1 (128 x 108) + GN stats ----------------
__global__ void out_conv1_kernel(const float* __restrict__ w1, const float* __restrict__ b1) {
    __shared__ float vt[108][64];
    int n0 = blockIdx.x * 64;
    int o  = threadIdx.x;  // 128
    for (int i = threadIdx.x; i < 108 * 64; i += 128) {
        int c = i / 64, nn = i % 64;
        vt[c][nn] = g_vfeat[(size_t)c * NPTS + n0 + nn];
    }
    __syncthreads();
    float bo = b1[o];
    float lsf = 0.f, ls2f = 0.f;
    for (int nb = 0; nb < 64; nb += 8) {
        float acc[8];
#pragma unroll
        for (int q = 0; q < 8; q++) acc[q] = bo;
        for (int c = 0; c < 108; c++) {
            float wv = __ldg(&w1[o * 108 + c]);
#pragma unroll
            for (int q = 0; q < 8; q++) acc[q] += wv * vt[c][nb + q];
        }
#pragma unroll
        for (int q = 0; q < 8; q++) {
            g_hout[(size_t)o * NPTS + n0 + nb + q] = acc[q];
            lsf  += acc[q];
            ls2f += acc[q] * acc[q];
        }
    }
    atomicAdd(&g_out_sum[o >> 4],  (double)lsf);
    atomicAdd(&g_out_sum2[o >> 4], (double)ls2f);
}

// ---------------- K7: finalize out GN stats ----------------
__global__ void finalize_out_kernel() {
    int t = threadIdx.x;
    if (t < 8) {
        double cnt = 16.0 * NPTS;
        double mu  = g_out_sum[t] / cnt;
        double var = g_out_sum2[t] / cnt - mu * mu;
        g_out_mu[t]  = (float)mu;
        g_out_inv[t] = (float)(1.0 / sqrt(var + 1e-5));
    }
}

// ---------------- K8: out GN+prelu + conv2 (64 x 128) -> d_out ----------------
__global__ void out_apply_kernel(const float* __restrict__ gma, const float* __restrict__ bta,
                                 const float* __restrict__ pr, const float* __restrict__ w2,
                                 const float* __restrict__ b2, float* __restrict__ out) {
    __shared__ float act[128][64];
    int n0 = blockIdx.x * 64;
    int t  = threadIdx.x;  // 256
    float a = pr[0];
    for (int i = t; i < 128 * 64; i += 256) {
        int ch = i / 64, nn = i % 64;
        float x = g_hout[(size_t)ch * NPTS + n0 + nn];
        int gr = ch >> 4;
        x = (x - g_out_mu[gr]) * g_out_inv[gr] * gma[ch] + bta[ch];
        act[ch][nn] = (x >= 0.f) ? x : a * x;
    }
    __syncthreads();
    for (int i = t; i < 64 * 64; i += 256) {
        int o = i / 64, nn = i % 64;
        float acc = b2[o];
        for (int c = 0; c < 128; c++) acc += w2[o * 128 + c] * act[c][nn];
        out[(size_t)o * NPTS + n0 + nn] = acc;
    }
}

// ---------------- K9: knn GN+prelu+max + conv (64x64), add into d_out ----------
__global__ void knn_apply_kernel(const float* __restrict__ w1, const float* __restrict__ b1,
                                 const float* __restrict__ gma, const float* __restrict__ bta,
                                 const float* __restrict__ pr, const float* __restrict__ ow,
                                 const float* __restrict__ ob, float* __restrict__ out) {
    __shared__ float s_kf[64];
    __shared__ float s_kin[KNN][4];
    int n = blockIdx.x;
    int t = threadIdx.x;  // 64
    for (int i = t; i < KNN * 4; i += 64)
        s_kin[i / 4][i % 4] = g_kin[(size_t)n * KNN * 4 + i];
    __syncthreads();
    {
        int ch = t;
        float a = pr[0];
        float w0 = w1[ch * 4 + 0], w1_ = w1[ch * 4 + 1], w2_ = w1[ch * 4 + 2], w3_ = w1[ch * 4 + 3];
        float bb = b1[ch];
        float mu = g_knn_mu[ch >> 3], inv = g_knn_inv[ch >> 3];
        float gg = gma[ch], bt_ = bta[ch];
        float mx = -INFINITY;
#pragma unroll
        for (int s = 0; s < KNN; s++) {
            float h = w0 * s_kin[s][0] + w1_ * s_kin[s][1] + w2_ * s_kin[s][2] + w3_ * s_kin[s][3] + bb;
            h = (h - mu) * inv * gg + bt_;
            h = (h >= 0.f) ? h : a * h;
            mx = fmaxf(mx, h);
        }
        s_kf[ch] = mx;
    }
    __syncthreads();
    {
        int o = t;
        float acc = ob[o];
#pragma unroll
        for (int c = 0; c < 64; c++) acc += ow[o * 64 + c] * s_kf[c];
        out[(size_t)o * NPTS + n] += acc;
    }
}

// ---------------- launch ----------------
extern "C" void kernel_launch(void* const* d_in, const int* in_sizes, int n_in,
                              void* d_out, int out_size) {
    const float* fmap1  = (const float*)d_in[0];
    const float* fmap2  = (const float*)d_in[1];
    const float* xyz2   = (const float*)d_in[2];
    const float* coords = (const float*)d_in[3];
    const float* out_w1 = (const float*)d_in[4];
    const float* out_b1 = (const float*)d_in[5];
    const float* out_g  = (const float*)d_in[6];
    const float* out_bt = (const float*)d_in[7];
    const float* out_pr = (const float*)d_in[8];
    const float* out_w2 = (const float*)d_in[9];
    const float* out_b2 = (const float*)d_in[10];
    const float* vox_w1 = (const float*)d_in[11];
    const float* vox_b1 = (const float*)d_in[12];
    const float* vox_g  = (const float*)d_in[13];
    const float* vox_bt = (const float*)d_in[14];
    const float* vox_pr = (const float*)d_in[15];
    const float* vox_w2 = (const float*)d_in[16];
    const float* vox_b2 = (const float*)d_in[17];
    const float* knn_w1 = (const float*)d_in[18];
    const float* knn_b1 = (const float*)d_in[19];
    const float* knn_g  = (const float*)d_in[20];
    const float* knn_bt = (const float*)d_in[21];
    const float* knn_pr = (const float*)d_in[22];
    const float* knn_ow = (const float*)d_in[23];
    const float* knn_ob = (const float*)d_in[24];
    float* out = (float*)d_out;

    cudaFuncSetAttribute(gemm_mma_kernel, cudaFuncAttributeMaxDynamicSharedMemorySize,
                         SM_GEMM_TOTAL);

    prep_kernel<<<dim3(NPTS / 64, 2), 256>>>(fmap1, fmap2);
    gemm_mma_kernel<<<dim3(NPTS / 128, NPTS / 128), 256, SM_GEMM_TOTAL>>>();
    topk_select_kernel<<<NPTS, 256>>>();
    topk_rerank_kernel<<<NPTS, 256>>>(xyz2);
    pointfeat_kernel<<<NPTS, 128>>>(coords, vox_w1, vox_b1, knn_w1, knn_b1);
    finalize_vk_kernel<<<1, 32>>>();
    vox_apply_kernel<<<(NPTS * 27 + 255) / 256, 256>>>(vox_w1, vox_b1, vox_g, vox_bt,
                                                       vox_pr, vox_w2, vox_b2);
    out_conv1_kernel<<<NPTS / 64, 128>>>(out_w1, out_b1);
    finalize_out_kernel<<<1, 32>>>();
    out_apply_kernel<<<NPTS / 64, 256>>>(out_g, out_bt, out_pr, out_w2, out_b2, out);
    knn_apply_kernel<<<NPTS, 64>>>(knn_w1, knn_b1, knn_g, knn_bt, knn_pr,
                                   knn_ow, knn_ob, out);
}

// round 11
// speedup vs baseline: 1.2984x; 1.2984x over previous
#include <cuda_runtime.h>
#include <cuda_bf16.h>
#include <math.h>
#include <stdint.h>

#define NPTS 8192
#define CCH  128
#define KSEL 128
#define KNN  32
#define KCAND 192      // approximate preselection size (slack 64 over KSEL)
#define CAND_CAP 768

// ---------------- scratch (device globals; no allocation) ----------------
__device__ __nv_bfloat16 g_corrh[(size_t)NPTS * NPTS]; // 128 MB approx corr
__device__ __nv_bfloat16 g_f1hi[(size_t)NPTS * CCH];   // [n][k] bf16
__device__ __nv_bfloat16 g_f2hi[(size_t)NPTS * CCH];
__device__ float  g_f1t[(size_t)NPTS * CCH];           // [n][k] fp32 (exact re-rank)
__device__ float  g_f2t[(size_t)NPTS * CCH];
__device__ unsigned g_cand[(size_t)NPTS * CAND_CAP];
__device__ unsigned g_ccnt[NPTS];
__device__ float  g_tcorr[NPTS * KSEL];
__device__ float  g_txyz[NPTS * KSEL * 3];
__device__ float  g_vfeat[108 * NPTS];
__device__ float  g_vcorr[NPTS * 27];
__device__ float  g_vxyz[NPTS * 27 * 3];
__device__ float  g_kin[NPTS * KNN * 4];
__device__ float  g_hout[128 * NPTS];

__device__ double g_vox_sum[8],  g_vox_sum2[8];
__device__ double g_knn_sum[8],  g_knn_sum2[8];
__device__ double g_out_sum[8],  g_out_sum2[8];
__device__ float  g_vox_mu[8], g_vox_inv[8];
__device__ float  g_knn_mu[8], g_knn_inv[8];
__device__ float  g_out_mu[8], g_out_inv[8];

// ---------------- helpers ----------------
__device__ __forceinline__ unsigned f2ord(float f) {
    unsigned u = __float_as_uint(f);
    return (u & 0x80000000u) ? ~u : (u | 0x80000000u);
}
__device__ __forceinline__ uint32_t smem_u32(const void* p) {
    uint32_t a;
    asm("{ .reg .u64 t; cvta.to.shared.u64 t, %1; cvt.u32.u64 %0, t; }" : "=r"(a) : "l"(p));
    return a;
}

// ---------------- Kp: transpose; write fp32 [n][k] + bf16 hi [n][k]; zero stats --
__global__ __launch_bounds__(256) void prep_kernel(const float* __restrict__ f1,
                                                   const float* __restrict__ f2) {
    __shared__ float tile[128][65];
    if (blockIdx.x == 0 && blockIdx.y == 0 && threadIdx.x < 8) {
        int q = threadIdx.x;
        g_vox_sum[q] = 0.0; g_vox_sum2[q] = 0.0;
        g_knn_sum[q] = 0.0; g_knn_sum2[q] = 0.0;
        g_out_sum[q] = 0.0; g_out_sum2[q] = 0.0;
    }
    const float* src = blockIdx.y ? f2 : f1;
    __nv_bfloat16* dhi = blockIdx.y ? g_f2hi : g_f1hi;
    float* dt = blockIdx.y ? g_f2t : g_f1t;
    int n0 = blockIdx.x * 64;
    int t = threadIdx.x;
    for (int i = t; i < 128 * 64; i += 256) {
        int n = i & 63;
        int k = i >> 6;
        tile[k][n] = src[(size_t)k * NPTS + n0 + n];
    }
    __syncthreads();
    for (int i = t; i < 64 * 128; i += 256) {
        int k = i & 127;
        int n = i >> 7;
        float v = tile[k][n];
        dt[(size_t)(n0 + n) * CCH + k]  = v;
        dhi[(size_t)(n0 + n) * CCH + k] = __float2bfloat16(v);
    }
}

// ---------------- K1: bf16 GEMM via mma.sync (HMMA), 128x128 per CTA, bf16 out --
#define TILE_BYTES 32768
#define SM_AHI 0
#define SM_BHI (SM_AHI + TILE_BYTES)
#define SM_GEMM_TOTAL (2 * TILE_BYTES)
#define SOUT 136   // bf16 elements per staged output row (272 B)

__device__ __forceinline__ uint32_t swz_off(int row, int chunk) {
    return (uint32_t)(row * 256 + ((chunk ^ (row & 7)) << 4));
}

__global__ __launch_bounds__(256) void gemm_mma_kernel() {
    extern __shared__ char smem[];
    uint32_t sbase = smem_u32(smem);
    int t = threadIdx.x;        // 256
    int bm = blockIdx.y * 128;
    int bn = blockIdx.x * 128;

#pragma unroll 1
    for (int tl = 0; tl < 2; tl++) {
        const __nv_bfloat16* sp = tl ? g_f2hi : g_f1hi;
        int srow = tl ? bn : bm;
        int soff = tl ? SM_BHI : SM_AHI;
        const uint4* src = (const uint4*)(sp + (size_t)srow * CCH);
#pragma unroll
        for (int it = 0; it < 8; it++) {
            int i   = t + it * 256;     // 0..2047
            int row = i >> 4;
            int chk = i & 15;
            uint4 v = src[(size_t)row * 16 + chk];
            *(uint4*)(smem + soff + swz_off(row, chk)) = v;
        }
    }
    __syncthreads();

    int wid  = t >> 5;
    int lane = t & 31;
    int wm = wid & 3;
    int wn = wid >> 2;
    int lrow = lane & 7;
    int lblk = lane >> 3;

    float acc[2][8][4];
#pragma unroll
    for (int i = 0; i < 2; i++)
#pragma unroll
        for (int j = 0; j < 8; j++)
#pragma unroll
            for (int q = 0; q < 4; q++) acc[i][j][q] = 0.f;

    uint32_t abase = sbase + SM_AHI;
    uint32_t bbase = sbase + SM_BHI;
#pragma unroll 1
    for (int ks = 0; ks < 8; ks++) {
        uint32_t a[2][4];
#pragma unroll
        for (int i = 0; i < 2; i++) {
            int row = wm * 32 + i * 16 + lrow + (lblk & 1) * 8;
            int chk = ks * 2 + (lblk >> 1);
            uint32_t addr = abase + swz_off(row, chk);
            asm volatile("ldmatrix.sync.aligned.m8n8.x4.shared.b16 {%0,%1,%2,%3}, [%4];"
                         : "=r"(a[i][0]), "=r"(a[i][1]), "=r"(a[i][2]), "=r"(a[i][3])
                         : "r"(addr));
        }
        uint32_t b[8][2];
#pragma unroll
        for (int jj = 0; jj < 4; jj++) {
            int row = wn * 64 + (jj * 2 + (lblk >> 1)) * 8 + lrow;
            int chk = ks * 2 + (lblk & 1);
            uint32_t addr = bbase + swz_off(row, chk);
            uint32_t r0, r1, r2, r3;
            asm volatile("ldmatrix.sync.aligned.m8n8.x4.shared.b16 {%0,%1,%2,%3}, [%4];"
                         : "=r"(r0), "=r"(r1), "=r"(r2), "=r"(r3)
                         : "r"(addr));
            b[jj * 2][0] = r0; b[jj * 2][1] = r1;
            b[jj * 2 + 1][0] = r2; b[jj * 2 + 1][1] = r3;
        }
#pragma unroll
        for (int i = 0; i < 2; i++)
#pragma unroll
            for (int j = 0; j < 8; j++) {
                asm volatile(
                    "mma.sync.aligned.m16n8k16.row.col.f32.bf16.bf16.f32 "
                    "{%0,%1,%2,%3}, {%4,%5,%6,%7}, {%8,%9}, {%0,%1,%2,%3};"
                    : "+f"(acc[i][j][0]), "+f"(acc[i][j][1]),
                      "+f"(acc[i][j][2]), "+f"(acc[i][j][3])
                    : "r"(a[i][0]), "r"(a[i][1]), "r"(a[i][2]), "r"(a[i][3]),
                      "r"(b[j][0]), "r"(b[j][1]));
            }
    }

    // ---- epilogue: stage into smem, then coalesced 256B rows ----
    __syncthreads();
    __nv_bfloat16* stile = (__nv_bfloat16*)smem;
    const float scale = 0.088388347648318447f;  // 1/sqrt(128)
#pragma unroll
    for (int i = 0; i < 2; i++) {
        int row0 = wm * 32 + i * 16 + (lane >> 2);
#pragma unroll
        for (int j = 0; j < 8; j++) {
            int col = wn * 64 + j * 8 + ((lane & 3) << 1);
            float2 v0, v1;
            v0.x = acc[i][j][0] * scale; v0.y = acc[i][j][1] * scale;
            v1.x = acc[i][j][2] * scale; v1.y = acc[i][j][3] * scale;
            *(__nv_bfloat162*)&stile[row0 * SOUT + col]       = __float22bfloat162_rn(v0);
            *(__nv_bfloat162*)&stile[(row0 + 8) * SOUT + col] = __float22bfloat162_rn(v1);
        }
    }
    __syncthreads();
#pragma unroll
    for (int it = 0; it < 8; it++) {
        int idx = t + it * 256;     // 0..2047
        int row = idx >> 4;
        int seg = idx & 15;
        uint4 v = *(const uint4*)&stile[row * SOUT + seg * 8];
        *(uint4*)&g_corrh[(size_t)(bm + row) * NPTS + bn + seg * 8] = v;
    }
}

// ---------------- K2a: top-KCAND preselect (12-bit hist + 4-bit refine) ---------
__global__ __launch_bounds__(256) void topk_select_kernel() {
    __shared__ unsigned s_key2[NPTS / 2];        // 16 KB packed ord16 pairs
    __shared__ unsigned s_hist[4096];            // 16 KB (12-bit bins)
    __shared__ unsigned s_gsum[256];             // 1 KB (group = 16 bins)
    __shared__ unsigned s_h16[16];
    __shared__ unsigned s_crossg, s_cumabove, s_bin12, s_cum12, s_thr, s_ccnt;

    int n = blockIdx.x;
    int t = threadIdx.x;  // 256

    for (int i = t; i < 4096; i += 256) s_hist[i] = 0;
    if (t == 0) s_ccnt = 0;
    if (t < 16) s_h16[t] = 0;
    __syncthreads();

    // pass A: load bf16 row, SIMD ord16 (both halves at once), 12-bit hist
    const uint4* rowp = (const uint4*)(g_corrh + (size_t)n * NPTS);
    for (int i = t; i < NPTS / 8; i += 256) {
        uint4 v = rowp[i];
        unsigned w[4] = {v.x, v.y, v.z, v.w};
#pragma unroll
        for (int q = 0; q < 4; q++) {
            unsigned vv = w[q];
            unsigned mask = (((vv >> 15) & 0x00010001u) * 0x7FFFu) | 0x80008000u;
            unsigned key2 = vv ^ mask;
            s_key2[i * 4 + q] = key2;
            atomicAdd(&s_hist[(key2 >> 4) & 0xFFFu], 1u);
            atomicAdd(&s_hist[key2 >> 20], 1u);
        }
    }
    __syncthreads();
    // group sums (16 bins each)
    {
        unsigned sum = 0;
#pragma unroll
        for (int b = 0; b < 16; b++) sum += s_hist[t * 16 + b];
        s_gsum[t] = sum;
    }
    __syncthreads();
    // warp 0: find crossing group via suffix scan (descending key order)
    if (t < 32) {
        int lane = t;
        int gtop = 255 - lane * 8;   // lane 0 owns the TOP 8 groups
        unsigned local = 0;
#pragma unroll
        for (int q = 0; q < 8; q++) local += s_gsum[gtop - q];
        unsigned pre = local;
#pragma unroll
        for (int d = 1; d < 32; d <<= 1) {
            unsigned other = __shfl_up_sync(0xFFFFFFFFu, pre, d);
            if (lane >= d) pre += other;
        }
        unsigned run = pre - local;  // count strictly above this lane's block
#pragma unroll
        for (int q = 0; q < 8; q++) {
            int g = gtop - q;
            unsigned c = s_gsum[g];
            if (run < KCAND && run + c >= KCAND) { s_crossg = (unsigned)g; s_cumabove = run; }
            run += c;
        }
    }
    __syncthreads();
    if (t == 0) {
        unsigned g = s_crossg;
        unsigned cum = s_cumabove;
        unsigned bin = g * 16;
        for (int b = 15; b >= 0; b--) {
            unsigned h = s_hist[g * 16 + b];
            if (cum + h >= KCAND) { bin = g * 16 + (unsigned)b; break; }
            cum += h;
        }
        s_bin12 = bin;
        s_cum12 = cum;
    }
    __syncthreads();
    // pass B: 4-bit refinement within the crossing 12-bit bin
    unsigned bin12 = s_bin12;
    for (int i = t; i < NPTS / 2; i += 256) {
        unsigned kk = s_key2[i];
        if (((kk >> 4) & 0xFFFu) == bin12) atomicAdd(&s_h16[kk & 0xFu], 1u);
        if ((kk >> 20) == bin12)           atomicAdd(&s_h16[(kk >> 16) & 0xFu], 1u);
    }
    __syncthreads();
    if (t == 0) {
        unsigned cum = s_cum12;
        unsigned thr = bin12 << 4;
        for (int b = 15; b >= 0; b--) {
            unsigned h = s_h16[b];
            if (cum + h >= KCAND) { thr = (bin12 << 4) | (unsigned)b; break; }
            cum += h;
        }
        s_thr = thr;
    }
    __syncthreads();
    unsigned thr = s_thr;
    // pass C: compact candidate indices (key >= thr), 2 keys per LDS
    for (int i = t; i < NPTS / 2; i += 256) {
        unsigned kk = s_key2[i];
        if ((kk & 0xFFFFu) >= thr) {
            unsigned ci = atomicAdd(&s_ccnt, 1u);
            if (ci < CAND_CAP) g_cand[(size_t)n * CAND_CAP + ci] = (unsigned)(i * 2);
        }
        if ((kk >> 16) >= thr) {
            unsigned ci = atomicAdd(&s_ccnt, 1u);
            if (ci < CAND_CAP) g_cand[(size_t)n * CAND_CAP + ci] = (unsigned)(i * 2 + 1);
        }
    }
    __syncthreads();
    if (t == 0) g_ccnt[n] = min(s_ccnt, (unsigned)CAND_CAP);
}

// ---------------- K2b: warp-per-candidate exact fp32 dots + packed rank ---------
__global__ __launch_bounds__(256) void topk_rerank_kernel(const float* __restrict__ xyz2) {
    __shared__ float    s_f1[CCH];
    __shared__ unsigned s_cidx[CAND_CAP];
    __shared__ float    s_val[CAND_CAP];
    __shared__ unsigned long long s_pk[CAND_CAP];

    int n = blockIdx.x;
    int t = threadIdx.x;  // 256
    unsigned C = g_ccnt[n];

    if (t < 128) s_f1[t] = g_f1t[(size_t)n * CCH + t];
    for (unsigned c = t; c < C; c += 256) s_cidx[c] = g_cand[(size_t)n * CAND_CAP + c];
    __syncthreads();

    int wid = t >> 5, lane = t & 31;
    const float scale = 0.088388347648318447f;
    float4 a = ((const float4*)s_f1)[lane];   // lane's 4-float segment of f1 row
    for (unsigned c = wid; c < C; c += 8) {
        unsigned m = s_cidx[c];
        float4 b = *(const float4*)(g_f2t + (size_t)m * CCH + lane * 4);
        float p = a.x * b.x + a.y * b.y + a.z * b.z + a.w * b.w;
        p += __shfl_xor_sync(0xFFFFFFFFu, p, 16);
        p += __shfl_xor_sync(0xFFFFFFFFu, p, 8);
        p += __shfl_xor_sync(0xFFFFFFFFu, p, 4);
        p += __shfl_xor_sync(0xFFFFFFFFu, p, 2);
        p += __shfl_xor_sync(0xFFFFFFFFu, p, 1);
        if (lane == 0) s_val[c] = p * scale;
    }
    __syncthreads();
    // packed rank keys: value desc, index asc
    for (unsigned c = t; c < C; c += 256)
        s_pk[c] = ((unsigned long long)f2ord(s_val[c]) << 32)
                | (unsigned long long)(8191u - s_cidx[c]);
    __syncthreads();

    for (unsigned c = t; c < C; c += 256) {
        unsigned long long kc = s_pk[c];
        unsigned r = 0;
        for (unsigned j = 0; j < C; j++) r += (s_pk[j] > kc) ? 1u : 0u;
        if (r < KSEL) {
            unsigned mc = s_cidx[c];
            g_tcorr[(size_t)n * KSEL + r] = s_val[c];
            size_t o = ((size_t)n * KSEL + r) * 3;
            g_txyz[o + 0] = xyz2[(size_t)mc * 3 + 0];
            g_txyz[o + 1] = xyz2[(size_t)mc * 3 + 1];
            g_txyz[o + 2] = xyz2[(size_t)mc * 3 + 2];
        }
    }
}

// ---------------- K3: per-point voxel levels + coarse stage + knn select + GN stats
__global__ __launch_bounds__(128) void pointfeat_kernel(const float* __restrict__ coords,
                                 const float* __restrict__ vw1, const float* __restrict__ vb1,
                                 const float* __restrict__ kw1, const float* __restrict__ kb1) {
    __shared__ float s_c[KSEL];
    __shared__ float s_x[KSEL][3];
    __shared__ float s_dd[KSEL];
    __shared__ float s_coord[3];
    __shared__ float s_add[27], s_cnt[27];
    __shared__ unsigned long long s_center[28];
    __shared__ float s_mv[27][3];
    __shared__ int   s_oob[27];
    __shared__ float s_cadd[28], s_ccnt[28];
    __shared__ float s_vcorr[27];
    __shared__ float s_kin[KNN][4];
    __shared__ float s_gs[8], s_gs2[8], s_kgs[8], s_kgs2[8];
    __shared__ unsigned long long s_top1key;

    int n = blockIdx.x;
    int t = threadIdx.x;  // 128

    s_c[t] = g_tcorr[(size_t)n * KSEL + t];
    {
        size_t o = ((size_t)n * KSEL + t) * 3;
        s_x[t][0] = g_txyz[o + 0];
        s_x[t][1] = g_txyz[o + 1];
        s_x[t][2] = g_txyz[o + 2];
    }
    if (t < 3) s_coord[t] = coords[(size_t)n * 3 + t];
    if (t == 0) s_top1key = 0ull;
    __syncthreads();
    float c0 = s_coord[0], c1 = s_coord[1], c2 = s_coord[2];
    float x0 = s_x[t][0], x1 = s_x[t][1], x2 = s_x[t][2];

    {
        float dx = x0 - c0, dy = x1 - c1, dz = x2 - c2;
        s_dd[t] = dx * dx + dy * dy + dz * dz;
        unsigned long long key =
            ((unsigned long long)f2ord(s_c[t]) << 32) | (unsigned)(127 - t);
        atomicMax(&s_top1key, key);
    }

    for (int lev = 0; lev < 3; lev++) {
        if (t < 27) { s_add[t] = 0.f; s_cnt[t] = 0.f; }
        __syncthreads();
        float r  = 0.25f * (float)(1 << lev);
        float d0 = rintf((x0 - c0) / r);
        float d1 = rintf((x1 - c1) / r);
        float d2 = rintf((x2 - c2) / r);
        if (fabsf(d0) <= 1.0f && fabsf(d1) <= 1.0f && fabsf(d2) <= 1.0f) {
            int cube = (int)((d0 + 1.f) * 9.f + (d1 + 1.f) * 3.f + (d2 + 1.f));
            atomicAdd(&s_add[cube], s_c[t]);
            atomicAdd(&s_cnt[cube], 1.f);
        }
        __syncthreads();
        if (t < 27)
            g_vfeat[(size_t)(lev * 27 + t) * NPTS + n] = s_add[t] / fmaxf(s_cnt[t], 1.f);
        __syncthreads();
    }

    if (t < 28) s_center[t] = 0ull;
    __syncthreads();
    {
        float d0 = rintf((x0 - c0) / 4.0f);
        float d1 = rintf((x1 - c1) / 4.0f);
        float d2 = rintf((x2 - c2) / 4.0f);
        if (fabsf(d0) <= 1.5f && fabsf(d1) <= 1.5f && fabsf(d2) <= 1.5f) {
            int b = (int)((d0 + 1.f) * 9.f + (d1 + 1.f) * 3.f + (d2 + 1.f)) + 1;
            unsigned long long key =
                ((unsigned long long)f2ord(s_c[t]) << 32) | (unsigned)(127 - t);
            atomicMax(&s_center[b], key);
        }
    }
    __syncthreads();
    int top1 = 127 - (int)(s_top1key & 0xFFFFFFFFu);
    if (t < 27) {
        unsigned long long k = s_center[t + 1];
        int oob, idx;
        if (k == 0ull) { oob = 1; idx = top1; }
        else {
            float v = __uint_as_float(((unsigned)(k >> 32) & 0x80000000u)
                        ? ((unsigned)(k >> 32) & 0x7FFFFFFFu)
                        : ~(unsigned)(k >> 32));
            oob = (v <= 0.f);
            idx = oob ? top1 : (127 - (int)(k & 0xFFFFFFFFu));
        }
        s_oob[t] = oob;
        float cc0 = s_x[idx][0], cc1 = s_x[idx][1], cc2 = s_x[idx][2];
        float bx = (float)((t / 9) % 3 - 1);
        float by = (float)((t / 3) % 3 - 1);
        float bz = (float)(t % 3 - 1);
        float vk0 = c0 + bx * 4.f, vk1 = c1 + by * 4.f, vk2 = c2 + bz * 4.f;
        float m0 = fminf(fmaxf(cc0 - vk0, -1.f), 1.f) + vk0;
        float m1 = fminf(fmaxf(cc1 - vk1, -1.f), 1.f) + vk1;
        float m2 = fminf(fmaxf(cc2 - vk2, -1.f), 1.f) + vk2;
        s_mv[t][0] = m0; s_mv[t][1] = m1; s_mv[t][2] = m2;
        size_t o = ((size_t)n * 27 + t) * 3;
        g_vxyz[o + 0] = m0; g_vxyz[o + 1] = m1; g_vxyz[o + 2] = m2;
    }
    if (t < 28) { s_cadd[t] = 0.f; s_ccnt[t] = 0.f; }
    __syncthreads();

    {
        int idx = 27;
        for (int k = 0; k < 27; k++) {
            if (!s_oob[k]) {
                if (fabsf((x0 - s_mv[k][0]) / 2.0f) <= 0.5f &&
                    fabsf((x1 - s_mv[k][1]) / 2.0f) <= 0.5f &&
                    fabsf((x2 - s_mv[k][2]) / 2.0f) <= 0.5f)
                    idx = k;
            }
        }
        atomicAdd(&s_cadd[idx], s_c[t]);
        atomicAdd(&s_ccnt[idx], 1.f);
    }
    {
        float dd = s_dd[t];
        int r = 0;
#pragma unroll 8
        for (int j = 0; j < KSEL; j++) {
            float dj = s_dd[j];
            r += (dj < dd || (dj == dd && j < t)) ? 1 : 0;
        }
        if (r < KNN) {
            float kc = s_c[t];
            float k0 = x0 - c0, k1 = x1 - c1, k2 = x2 - c2;
            s_kin[r][0] = kc; s_kin[r][1] = k0; s_kin[r][2] = k1; s_kin[r][3] = k2;
            size_t o = ((size_t)n * KNN + r) * 4;
            g_kin[o] = kc; g_kin[o + 1] = k0; g_kin[o + 2] = k1; g_kin[o + 3] = k2;
        }
    }
    __syncthreads();
    if (t < 27) {
        float vc = s_cadd[t] / fmaxf(s_ccnt[t], 1.f);
        s_vcorr[t] = vc;
        g_vcorr[(size_t)n * 27 + t] = vc;
    }
    __syncthreads();

    if (t >= 64 && t < 96) {
        int ch = t - 64;
        float w0 = vw1[ch * 4 + 0], w1_ = vw1[ch * 4 + 1];
        float w2_ = vw1[ch * 4 + 2], w3_ = vw1[ch * 4 + 3];
        float bb = vb1[ch];
        float sum = 0.f, sum2 = 0.f;
#pragma unroll
        for (int k = 0; k < 27; k++) {
            float h = w0 * s_vcorr[k] + w1_ * s_mv[k][0] + w2_ * s_mv[k][1] + w3_ * s_mv[k][2] + bb;
            sum += h; sum2 += h * h;
        }
        sum  += __shfl_xor_sync(0xFFFFFFFFu, sum, 1);
        sum2 += __shfl_xor_sync(0xFFFFFFFFu, sum2, 1);
        sum  += __shfl_xor_sync(0xFFFFFFFFu, sum, 2);
        sum2 += __shfl_xor_sync(0xFFFFFFFFu, sum2, 2);
        if ((ch & 3) == 0) { s_gs[ch >> 2] = sum; s_gs2[ch >> 2] = sum2; }
    }
    if (t < 64) {
        int ch = t;
        float w0 = kw1[ch * 4 + 0], w1_ = kw1[ch * 4 + 1];
        float w2_ = kw1[ch * 4 + 2], w3_ = kw1[ch * 4 + 3];
        float bb = kb1[ch];
        float sum = 0.f, sum2 = 0.f;
#pragma unroll
        for (int s = 0; s < KNN; s++) {
            float h = w0 * s_kin[s][0] + w1_ * s_kin[s][1] + w2_ * s_kin[s][2] + w3_ * s_kin[s][3] + bb;
            sum += h; sum2 += h * h;
        }
        sum  += __shfl_xor_sync(0xFFFFFFFFu, sum, 1);
        sum2 += __shfl_xor_sync(0xFFFFFFFFu, sum2, 1);
        sum  += __shfl_xor_sync(0xFFFFFFFFu, sum, 2);
        sum2 += __shfl_xor_sync(0xFFFFFFFFu, sum2, 2);
        sum  += __shfl_xor_sync(0xFFFFFFFFu, sum, 4);
        sum2 += __shfl_xor_sync(0xFFFFFFFFu, sum2, 4);
        if ((ch & 7) == 0) { s_kgs[ch >> 3] = sum; s_kgs2[ch >> 3] = sum2; }
    }
    __syncthreads();
    if (t < 8) {
        atomicAdd(&g_vox_sum[t],  (double)s_gs[t]);
        atomicAdd(&g_vox_sum2[t], (double)s_gs2[t]);
        atomicAdd(&g_knn_sum[t],  (double)s_kgs[t]);
        atomicAdd(&g_knn_sum2[t], (double)s_kgs2[t]);
    }
}

// ---------------- K4: finalize vox + knn GN stats ----------------
__global__ void finalize_vk_kernel() {
    int t = threadIdx.x;
    if (t < 8) {
        double cnt = 4.0 * NPTS * 27.0;
        double mu  = g_vox_sum[t] / cnt;
        double var = g_vox_sum2[t] / cnt - mu * mu;
        g_vox_mu[t]  = (float)mu;
        g_vox_inv[t] = (float)(1.0 / sqrt(var + 1e-5));
    } else if (t < 16) {
        int g = t - 8;
        double cnt = 8.0 * NPTS * (double)KNN;
        double mu  = g_knn_sum[g] / cnt;
        double var = g_knn_sum2[g] / cnt - mu * mu;
        g_knn_mu[g]  = (float)mu;
        g_knn_inv[g] = (float)(1.0 / sqrt(var + 1e-5));
    }
}

// ---------------- K5: vox MLP apply -> vfeat channels 81..107 ----------------
__global__ void vox_apply_kernel(const float* __restrict__ w1, const float* __restrict__ b1,
                                 const float* __restrict__ gma, const float* __restrict__ bta,
                                 const float* __restrict__ pr, const float* __restrict__ w2,
                                 const float* __restrict__ b2) {
    int idx = blockIdx.x * blockDim.x + threadIdx.x;
    if (idx >= NPTS * 27) return;
    int n = idx / 27, k = idx % 27;
    float vc = g_vcorr[idx];
    float m0 = g_vxyz[(size_t)idx * 3 + 0];
    float m1 = g_vxyz[(size_t)idx * 3 + 1];
    float m2 = g_vxyz[(size_t)idx * 3 + 2];
    float a = pr[0];
    float acc = b2[0];
#pragma unroll
    for (int ch = 0; ch < 32; ch++) {
        float h = w1[ch * 4 + 0] * vc + w1[ch * 4 + 1] * m0
                + w1[ch * 4 + 2] * m1 + w1[ch * 4 + 3] * m2 + b1[ch];
        int gr = ch >> 2;
        h = (h - g_vox_mu[gr]) * g_vox_inv[gr] * gma[ch] + bta[ch];
        h = (h >= 0.f) ? h : a * h;
        acc += w2[ch] * h;
    }
    g_vfeat[(size_t)(81 + k) * NPTS + n] = acc;
}

// ---------------- K6: out conv1 (128 x 108) + GN stats ----------------
__global__ void out_conv1_kernel(const float* __restrict__ w1, const float* __restrict__ b1) {
    __shared__ float vt[108][64];
    int n0 = blockIdx.x * 64;
    int o  = threadIdx.x;  // 128
    for (int i = threadIdx.x; i < 108 * 64; i += 128) {
        int c = i / 64, nn = i % 64;
        vt[c][nn] = g_vfeat[(size_t)c * NPTS + n0 + nn];
    }
    __syncthreads();
    float bo = b1[o];
    float lsf = 0.f, ls2f = 0.f;
    for (int nb = 0; nb < 64; nb += 8) {
        float acc[8];
#pragma unroll
        for (int q = 0; q < 8; q++) acc[q] = bo;
        for (int c = 0; c < 108; c++) {
            float wv = __ldg(&w1[o * 108 + c]);
#pragma unroll
            for (int q = 0; q < 8; q++) acc[q] += wv * vt[c][nb + q];
        }
#pragma unroll
        for (int q = 0; q < 8; q++) {
            g_hout[(size_t)o * NPTS + n0 + nb + q] = acc[q];
            lsf  += acc[q];
            ls2f += acc[q] * acc[q];
        }
    }
    atomicAdd(&g_out_sum[o >> 4],  (double)lsf);
    atomicAdd(&g_out_sum2[o >> 4], (double)ls2f);
}

// ---------------- K7: finalize out GN stats ----------------
__global__ void finalize_out_kernel() {
    int t = threadIdx.x;
    if (t < 8) {
        double cnt = 16.0 * NPTS;
        double mu  = g_out_sum[t] / cnt;
        double var = g_out_sum2[t] / cnt - mu * mu;
        g_out_mu[t]  = (float)mu;
        g_out_inv[t] = (float)(1.0 / sqrt(var + 1e-5));
    }
}

// ---------------- K8: out GN+prelu + conv2 (64 x 128) -> d_out ----------------
__global__ void out_apply_kernel(const float* __restrict__ gma, const float* __restrict__ bta,
                                 const float* __restrict__ pr, const float* __restrict__ w2,
                                 const float* __restrict__ b2, float* __restrict__ out) {
    __shared__ float act[128][64];
    int n0 = blockIdx.x * 64;
    int t  = threadIdx.x;  // 256
    float a = pr[0];
    for (int i = t; i < 128 * 64; i += 256) {
        int ch = i / 64, nn = i % 64;
        float x = g_hout[(size_t)ch * NPTS + n0 + nn];
        int gr = ch >> 4;
        x = (x - g_out_mu[gr]) * g_out_inv[gr] * gma[ch] + bta[ch];
        act[ch][nn] = (x >= 0.f) ? x : a * x;
    }
    __syncthreads();
    for (int i = t; i < 64 * 64; i += 256) {
        int o = i / 64, nn = i % 64;
        float acc = b2[o];
        for (int c = 0; c < 128; c++) acc += w2[o * 128 + c] * act[c][nn];
        out[(size_t)o * NPTS + n0 + nn] = acc;
    }
}

// ---------------- K9: knn GN+prelu+max + conv (64x64), add into d_out ----------
__global__ void knn_apply_kernel(const float* __restrict__ w1, const float* __restrict__ b1,
                                 const float* __restrict__ gma, const float* __restrict__ bta,
                                 const float* __restrict__ pr, const float* __restrict__ ow,
                                 const float* __restrict__ ob, float* __restrict__ out) {
    __shared__ float s_kf[64];
    __shared__ float s_kin[KNN][4];
    int n = blockIdx.x;
    int t = threadIdx.x;  // 64
    for (int i = t; i < KNN * 4; i += 64)
        s_kin[i / 4][i % 4] = g_kin[(size_t)n * KNN * 4 + i];
    __syncthreads();
    {
        int ch = t;
        float a = pr[0];
        float w0 = w1[ch * 4 + 0], w1_ = w1[ch * 4 + 1], w2_ = w1[ch * 4 + 2], w3_ = w1[ch * 4 + 3];
        float bb = b1[ch];
        float mu = g_knn_mu[ch >> 3], inv = g_knn_inv[ch >> 3];
        float gg = gma[ch], bt_ = bta[ch];
        float mx = -INFINITY;
#pragma unroll
        for (int s = 0; s < KNN; s++) {
            float h = w0 * s_kin[s][0] + w1_ * s_kin[s][1] + w2_ * s_kin[s][2] + w3_ * s_kin[s][3] + bb;
            h = (h - mu) * inv * gg + bt_;
            h = (h >= 0.f) ? h : a * h;
            mx = fmaxf(mx, h);
        }
        s_kf[ch] = mx;
    }
    __syncthreads();
    {
        int o = t;
        float acc = ob[o];
#pragma unroll
        for (int c = 0; c < 64; c++) acc += ow[o * 64 + c] * s_kf[c];
        out[(size_t)o * NPTS + n] += acc;
    }
}

// ---------------- launch ----------------
extern "C" void kernel_launch(void* const* d_in, const int* in_sizes, int n_in,
                              void* d_out, int out_size) {
    const float* fmap1  = (const float*)d_in[0];
    const float* fmap2  = (const float*)d_in[1];
    const float* xyz2   = (const float*)d_in[2];
    const float* coords = (const float*)d_in[3];
    const float* out_w1 = (const float*)d_in[4];
    const float* out_b1 = (const float*)d_in[5];
    const float* out_g  = (const float*)d_in[6];
    const float* out_bt = (const float*)d_in[7];
    const float* out_pr = (const float*)d_in[8];
    const float* out_w2 = (const float*)d_in[9];
    const float* out_b2 = (const float*)d_in[10];
    const float* vox_w1 = (const float*)d_in[11];
    const float* vox_b1 = (const float*)d_in[12];
    const float* vox_g  = (const float*)d_in[13];
    const float* vox_bt = (const float*)d_in[14];
    const float* vox_pr = (const float*)d_in[15];
    const float* vox_w2 = (const float*)d_in[16];
    const float* vox_b2 = (const float*)d_in[17];
    const float* knn_w1 = (const float*)d_in[18];
    const float* knn_b1 = (const float*)d_in[19];
    const float* knn_g  = (const float*)d_in[20];
    const float* knn_bt = (const float*)d_in[21];
    const float* knn_pr = (const float*)d_in[22];
    const float* knn_ow = (const float*)d_in[23];
    const float* knn_ob = (const float*)d_in[24];
    float* out = (float*)d_out;

    cudaFuncSetAttribute(gemm_mma_kernel, cudaFuncAttributeMaxDynamicSharedMemorySize,
                         SM_GEMM_TOTAL);

    prep_kernel<<<dim3(NPTS / 64, 2), 256>>>(fmap1, fmap2);
    gemm_mma_kernel<<<dim3(NPTS / 128, NPTS / 128), 256, SM_GEMM_TOTAL>>>();
    topk_select_kernel<<<NPTS, 256>>>();
    topk_rerank_kernel<<<NPTS, 256>>>(xyz2);
    pointfeat_kernel<<<NPTS, 128>>>(coords, vox_w1, vox_b1, knn_w1, knn_b1);
    finalize_vk_kernel<<<1, 32>>>();
    vox_apply_kernel<<<(NPTS * 27 + 255) / 256, 256>>>(vox_w1, vox_b1, vox_g, vox_bt,
                                                       vox_pr, vox_w2, vox_b2);
    out_conv1_kernel<<<NPTS / 64, 128>>>(out_w1, out_b1);
    finalize_out_kernel<<<1, 32>>>();
    out_apply_kernel<<<NPTS / 64, 256>>>(out_g, out_bt, out_pr, out_w2, out_b2, out);
    knn_apply_kernel<<<NPTS, 64>>>(knn_w1, knn_b1, knn_g, knn_bt, knn_pr,
                                   knn_ow, knn_ob, out);
}

// round 12
// speedup vs baseline: 1.3410x; 1.0328x over previous
#include <cuda_runtime.h>
#include <cuda_bf16.h>
#include <math.h>
#include <stdint.h>

#define NPTS 8192
#define CCH  128
#define KSEL 128
#define KNN  32
#define KCAND 192      // approximate preselection size (slack 64 over KSEL)
#define CAND_CAP 768

// ---------------- scratch (device globals; no allocation) ----------------
__device__ __nv_bfloat16 g_corrh[(size_t)NPTS * NPTS]; // 128 MB approx corr
__device__ __nv_bfloat16 g_f1hi[(size_t)NPTS * CCH];   // [n][k] bf16
__device__ __nv_bfloat16 g_f2hi[(size_t)NPTS * CCH];
__device__ float  g_f1t[(size_t)NPTS * CCH];           // [n][k] fp32 (exact re-rank)
__device__ float  g_f2t[(size_t)NPTS * CCH];
__device__ float  g_tcorr[NPTS * KSEL];
__device__ float  g_txyz[NPTS * KSEL * 3];
__device__ float  g_vfeat[108 * NPTS];
__device__ float  g_vcorr[NPTS * 27];
__device__ float  g_vxyz[NPTS * 27 * 3];
__device__ float  g_kin[NPTS * KNN * 4];
__device__ float  g_hout[128 * NPTS];

__device__ double g_vox_sum[8],  g_vox_sum2[8];
__device__ double g_knn_sum[8],  g_knn_sum2[8];
__device__ double g_out_sum[8],  g_out_sum2[8];
__device__ float  g_vox_mu[8], g_vox_inv[8];
__device__ float  g_knn_mu[8], g_knn_inv[8];
__device__ float  g_out_mu[8], g_out_inv[8];

// ---------------- helpers ----------------
__device__ __forceinline__ unsigned f2ord(float f) {
    unsigned u = __float_as_uint(f);
    return (u & 0x80000000u) ? ~u : (u | 0x80000000u);
}
__device__ __forceinline__ uint32_t smem_u32(const void* p) {
    uint32_t a;
    asm("{ .reg .u64 t; cvta.to.shared.u64 t, %1; cvt.u32.u64 %0, t; }" : "=r"(a) : "l"(p));
    return a;
}

// ---------------- Kp: transpose; write fp32 [n][k] + bf16 hi [n][k]; zero stats --
__global__ __launch_bounds__(256) void prep_kernel(const float* __restrict__ f1,
                                                   const float* __restrict__ f2) {
    __shared__ float tile[128][65];
    if (blockIdx.x == 0 && blockIdx.y == 0 && threadIdx.x < 8) {
        int q = threadIdx.x;
        g_vox_sum[q] = 0.0; g_vox_sum2[q] = 0.0;
        g_knn_sum[q] = 0.0; g_knn_sum2[q] = 0.0;
        g_out_sum[q] = 0.0; g_out_sum2[q] = 0.0;
    }
    const float* src = blockIdx.y ? f2 : f1;
    __nv_bfloat16* dhi = blockIdx.y ? g_f2hi : g_f1hi;
    float* dt = blockIdx.y ? g_f2t : g_f1t;
    int n0 = blockIdx.x * 64;
    int t = threadIdx.x;
    for (int i = t; i < 128 * 64; i += 256) {
        int n = i & 63;
        int k = i >> 6;
        tile[k][n] = src[(size_t)k * NPTS + n0 + n];
    }
    __syncthreads();
    for (int i = t; i < 64 * 128; i += 256) {
        int k = i & 127;
        int n = i >> 7;
        float v = tile[k][n];
        dt[(size_t)(n0 + n) * CCH + k]  = v;
        dhi[(size_t)(n0 + n) * CCH + k] = __float2bfloat16(v);
    }
}

// ---------------- K1: bf16 GEMM via mma.sync (HMMA), 128x128 per CTA, bf16 out --
#define TILE_BYTES 32768
#define SM_AHI 0
#define SM_BHI (SM_AHI + TILE_BYTES)
#define SM_GEMM_TOTAL (2 * TILE_BYTES)
#define SOUT 136   // bf16 elements per staged output row (272 B)

__device__ __forceinline__ uint32_t swz_off(int row, int chunk) {
    return (uint32_t)(row * 256 + ((chunk ^ (row & 7)) << 4));
}

__global__ __launch_bounds__(256) void gemm_mma_kernel() {
    extern __shared__ char smem[];
    uint32_t sbase = smem_u32(smem);
    int t = threadIdx.x;        // 256
    int bm = blockIdx.y * 128;
    int bn = blockIdx.x * 128;

#pragma unroll 1
    for (int tl = 0; tl < 2; tl++) {
        const __nv_bfloat16* sp = tl ? g_f2hi : g_f1hi;
        int srow = tl ? bn : bm;
        int soff = tl ? SM_BHI : SM_AHI;
        const uint4* src = (const uint4*)(sp + (size_t)srow * CCH);
#pragma unroll
        for (int it = 0; it < 8; it++) {
            int i   = t + it * 256;     // 0..2047
            int row = i >> 4;
            int chk = i & 15;
            uint4 v = src[(size_t)row * 16 + chk];
            *(uint4*)(smem + soff + swz_off(row, chk)) = v;
        }
    }
    __syncthreads();

    int wid  = t >> 5;
    int lane = t & 31;
    int wm = wid & 3;
    int wn = wid >> 2;
    int lrow = lane & 7;
    int lblk = lane >> 3;

    float acc[2][8][4];
#pragma unroll
    for (int i = 0; i < 2; i++)
#pragma unroll
        for (int j = 0; j < 8; j++)
#pragma unroll
            for (int q = 0; q < 4; q++) acc[i][j][q] = 0.f;

    uint32_t abase = sbase + SM_AHI;
    uint32_t bbase = sbase + SM_BHI;
#pragma unroll 1
    for (int ks = 0; ks < 8; ks++) {
        uint32_t a[2][4];
#pragma unroll
        for (int i = 0; i < 2; i++) {
            int row = wm * 32 + i * 16 + lrow + (lblk & 1) * 8;
            int chk = ks * 2 + (lblk >> 1);
            uint32_t addr = abase + swz_off(row, chk);
            asm volatile("ldmatrix.sync.aligned.m8n8.x4.shared.b16 {%0,%1,%2,%3}, [%4];"
                         : "=r"(a[i][0]), "=r"(a[i][1]), "=r"(a[i][2]), "=r"(a[i][3])
                         : "r"(addr));
        }
        uint32_t b[8][2];
#pragma unroll
        for (int jj = 0; jj < 4; jj++) {
            int row = wn * 64 + (jj * 2 + (lblk >> 1)) * 8 + lrow;
            int chk = ks * 2 + (lblk & 1);
            uint32_t addr = bbase + swz_off(row, chk);
            uint32_t r0, r1, r2, r3;
            asm volatile("ldmatrix.sync.aligned.m8n8.x4.shared.b16 {%0,%1,%2,%3}, [%4];"
                         : "=r"(r0), "=r"(r1), "=r"(r2), "=r"(r3)
                         : "r"(addr));
            b[jj * 2][0] = r0; b[jj * 2][1] = r1;
            b[jj * 2 + 1][0] = r2; b[jj * 2 + 1][1] = r3;
        }
#pragma unroll
        for (int i = 0; i < 2; i++)
#pragma unroll
            for (int j = 0; j < 8; j++) {
                asm volatile(
                    "mma.sync.aligned.m16n8k16.row.col.f32.bf16.bf16.f32 "
                    "{%0,%1,%2,%3}, {%4,%5,%6,%7}, {%8,%9}, {%0,%1,%2,%3};"
                    : "+f"(acc[i][j][0]), "+f"(acc[i][j][1]),
                      "+f"(acc[i][j][2]), "+f"(acc[i][j][3])
                    : "r"(a[i][0]), "r"(a[i][1]), "r"(a[i][2]), "r"(a[i][3]),
                      "r"(b[j][0]), "r"(b[j][1]));
            }
    }

    // ---- epilogue: stage into smem, then coalesced 256B rows ----
    __syncthreads();
    __nv_bfloat16* stile = (__nv_bfloat16*)smem;
    const float scale = 0.088388347648318447f;  // 1/sqrt(128)
#pragma unroll
    for (int i = 0; i < 2; i++) {
        int row0 = wm * 32 + i * 16 + (lane >> 2);
#pragma unroll
        for (int j = 0; j < 8; j++) {
            int col = wn * 64 + j * 8 + ((lane & 3) << 1);
            float2 v0, v1;
            v0.x = acc[i][j][0] * scale; v0.y = acc[i][j][1] * scale;
            v1.x = acc[i][j][2] * scale; v1.y = acc[i][j][3] * scale;
            *(__nv_bfloat162*)&stile[row0 * SOUT + col]       = __float22bfloat162_rn(v0);
            *(__nv_bfloat162*)&stile[(row0 + 8) * SOUT + col] = __float22bfloat162_rn(v1);
        }
    }
    __syncthreads();
#pragma unroll
    for (int it = 0; it < 8; it++) {
        int idx = t + it * 256;     // 0..2047
        int row = idx >> 4;
        int seg = idx & 15;
        uint4 v = *(const uint4*)&stile[row * SOUT + seg * 8];
        *(uint4*)&g_corrh[(size_t)(bm + row) * NPTS + bn + seg * 8] = v;
    }
}

// ---------------- K2: fused preselect (12-bit + 4-bit refine) + exact re-rank ---
__global__ __launch_bounds__(256) void topk_kernel(const float* __restrict__ xyz2) {
    __shared__ unsigned s_key2[NPTS / 2];        // 16 KB packed ord16 pairs
    __shared__ unsigned s_hist[4096];            // 16 KB (12-bit bins)
    __shared__ unsigned s_gsum[256];             // 1 KB (group = 16 bins)
    __shared__ unsigned s_h16[16];
    __shared__ float    s_f1[CCH];               // 0.5 KB
    __shared__ unsigned s_cidx[CAND_CAP];        // 3 KB
    __shared__ float    s_val[CAND_CAP];         // 3 KB
    __shared__ unsigned long long s_pk[CAND_CAP];// 6 KB
    __shared__ unsigned s_crossg, s_cumabove, s_bin12, s_cum12, s_thr, s_ccnt;

    int n = blockIdx.x;
    int t = threadIdx.x;  // 256

    for (int i = t; i < 4096; i += 256) s_hist[i] = 0;
    if (t < 128) s_f1[t] = g_f1t[(size_t)n * CCH + t];
    if (t == 0) s_ccnt = 0;
    if (t >= 240) s_h16[t - 240] = 0;
    __syncthreads();

    // pass A: load bf16 row, SIMD ord16 (both halves at once), 12-bit hist
    const uint4* rowp = (const uint4*)(g_corrh + (size_t)n * NPTS);
    for (int i = t; i < NPTS / 8; i += 256) {
        uint4 v = rowp[i];
        unsigned w[4] = {v.x, v.y, v.z, v.w};
#pragma unroll
        for (int q = 0; q < 4; q++) {
            unsigned vv = w[q];
            unsigned mask = (((vv >> 15) & 0x00010001u) * 0x7FFFu) | 0x80008000u;
            unsigned key2 = vv ^ mask;
            s_key2[i * 4 + q] = key2;
            atomicAdd(&s_hist[(key2 >> 4) & 0xFFFu], 1u);
            atomicAdd(&s_hist[key2 >> 20], 1u);
        }
    }
    __syncthreads();
    // group sums (16 bins each)
    {
        unsigned sum = 0;
#pragma unroll
        for (int b = 0; b < 16; b++) sum += s_hist[t * 16 + b];
        s_gsum[t] = sum;
    }
    __syncthreads();
    // warp 0: find crossing group via suffix scan (descending key order)
    if (t < 32) {
        int lane = t;
        int gtop = 255 - lane * 8;   // lane 0 owns the TOP 8 groups
        unsigned local = 0;
#pragma unroll
        for (int q = 0; q < 8; q++) local += s_gsum[gtop - q];
        unsigned pre = local;
#pragma unroll
        for (int d = 1; d < 32; d <<= 1) {
            unsigned other = __shfl_up_sync(0xFFFFFFFFu, pre, d);
            if (lane >= d) pre += other;
        }
        unsigned run = pre - local;  // count strictly above this lane's block
#pragma unroll
        for (int q = 0; q < 8; q++) {
            int g = gtop - q;
            unsigned c = s_gsum[g];
            if (run < KCAND && run + c >= KCAND) { s_crossg = (unsigned)g; s_cumabove = run; }
            run += c;
        }
    }
    __syncthreads();
    if (t == 0) {
        unsigned g = s_crossg;
        unsigned cum = s_cumabove;
        unsigned bin = g * 16;
        for (int b = 15; b >= 0; b--) {
            unsigned h = s_hist[g * 16 + b];
            if (cum + h >= KCAND) { bin = g * 16 + (unsigned)b; break; }
            cum += h;
        }
        s_bin12 = bin;
        s_cum12 = cum;
    }
    __syncthreads();
    // pass B: 4-bit refinement within the crossing 12-bit bin
    unsigned bin12 = s_bin12;
    for (int i = t; i < NPTS / 2; i += 256) {
        unsigned kk = s_key2[i];
        if (((kk >> 4) & 0xFFFu) == bin12) atomicAdd(&s_h16[kk & 0xFu], 1u);
        if ((kk >> 20) == bin12)           atomicAdd(&s_h16[(kk >> 16) & 0xFu], 1u);
    }
    __syncthreads();
    if (t == 0) {
        unsigned cum = s_cum12;
        unsigned thr = bin12 << 4;
        for (int b = 15; b >= 0; b--) {
            unsigned h = s_h16[b];
            if (cum + h >= KCAND) { thr = (bin12 << 4) | (unsigned)b; break; }
            cum += h;
        }
        s_thr = thr;
    }
    __syncthreads();
    unsigned thr = s_thr;
    // pass C: compact candidate indices (key >= thr) into smem
    for (int i = t; i < NPTS / 2; i += 256) {
        unsigned kk = s_key2[i];
        if ((kk & 0xFFFFu) >= thr) {
            unsigned ci = atomicAdd(&s_ccnt, 1u);
            if (ci < CAND_CAP) s_cidx[ci] = (unsigned)(i * 2);
        }
        if ((kk >> 16) >= thr) {
            unsigned ci = atomicAdd(&s_ccnt, 1u);
            if (ci < CAND_CAP) s_cidx[ci] = (unsigned)(i * 2 + 1);
        }
    }
    __syncthreads();
    unsigned C = min(s_ccnt, (unsigned)CAND_CAP);

    // exact fp32 dots: 4 candidates per warp, 8-lane groups, 3-shfl reduce
    {
        int wid = t >> 5, lane = t & 31;
        int grp = lane >> 3, gl = lane & 7;
        const float4* f1v = (const float4*)s_f1;
        float4 a0 = f1v[gl];
        float4 a1 = f1v[gl + 8];
        float4 a2 = f1v[gl + 16];
        float4 a3 = f1v[gl + 24];
        const float scale = 0.088388347648318447f;
        for (unsigned cb = (unsigned)wid * 4; cb < C; cb += 32) {
            unsigned c = cb + (unsigned)grp;
            unsigned m = s_cidx[(c < C) ? c : 0];
            const float4* f2 = (const float4*)(g_f2t + (size_t)m * CCH);
            float4 b0 = f2[gl], b1 = f2[gl + 8], b2 = f2[gl + 16], b3 = f2[gl + 24];
            float p = a0.x * b0.x + a0.y * b0.y + a0.z * b0.z + a0.w * b0.w
                    + a1.x * b1.x + a1.y * b1.y + a1.z * b1.z + a1.w * b1.w
                    + a2.x * b2.x + a2.y * b2.y + a2.z * b2.z + a2.w * b2.w
                    + a3.x * b3.x + a3.y * b3.y + a3.z * b3.z + a3.w * b3.w;
            p += __shfl_xor_sync(0xFFFFFFFFu, p, 4);
            p += __shfl_xor_sync(0xFFFFFFFFu, p, 2);
            p += __shfl_xor_sync(0xFFFFFFFFu, p, 1);
            if (gl == 0 && c < C) s_val[c] = p * scale;
        }
    }
    __syncthreads();
    // packed rank keys: value desc, index asc
    for (unsigned c = t; c < C; c += 256)
        s_pk[c] = ((unsigned long long)f2ord(s_val[c]) << 32)
                | (unsigned long long)(8191u - s_cidx[c]);
    __syncthreads();

    for (unsigned c = t; c < C; c += 256) {
        unsigned long long kc = s_pk[c];
        unsigned r = 0;
        for (unsigned j = 0; j < C; j++) r += (s_pk[j] > kc) ? 1u : 0u;
        if (r < KSEL) {
            unsigned mc = s_cidx[c];
            g_tcorr[(size_t)n * KSEL + r] = s_val[c];
            size_t o = ((size_t)n * KSEL + r) * 3;
            g_txyz[o + 0] = xyz2[(size_t)mc * 3 + 0];
            g_txyz[o + 1] = xyz2[(size_t)mc * 3 + 1];
            g_txyz[o + 2] = xyz2[(size_t)mc * 3 + 2];
        }
    }
}

// ---------------- K3: per-point voxel levels + coarse stage + knn select + GN stats
__global__ __launch_bounds__(128) void pointfeat_kernel(const float* __restrict__ coords,
                                 const float* __restrict__ vw1, const float* __restrict__ vb1,
                                 const float* __restrict__ kw1, const float* __restrict__ kb1) {
    __shared__ float s_c[KSEL];
    __shared__ float s_x[KSEL][3];
    __shared__ float s_dd[KSEL];
    __shared__ float s_coord[3];
    __shared__ float s_add[27], s_cnt[27];
    __shared__ unsigned long long s_center[28];
    __shared__ float s_mv[27][3];
    __shared__ int   s_oob[27];
    __shared__ float s_cadd[28], s_ccnt[28];
    __shared__ float s_vcorr[27];
    __shared__ float s_kin[KNN][4];
    __shared__ float s_gs[8], s_gs2[8], s_kgs[8], s_kgs2[8];
    __shared__ unsigned long long s_top1key;

    int n = blockIdx.x;
    int t = threadIdx.x;  // 128

    s_c[t] = g_tcorr[(size_t)n * KSEL + t];
    {
        size_t o = ((size_t)n * KSEL + t) * 3;
        s_x[t][0] = g_txyz[o + 0];
        s_x[t][1] = g_txyz[o + 1];
        s_x[t][2] = g_txyz[o + 2];
    }
    if (t < 3) s_coord[t] = coords[(size_t)n * 3 + t];
    if (t == 0) s_top1key = 0ull;
    __syncthreads();
    float c0 = s_coord[0], c1 = s_coord[1], c2 = s_coord[2];
    float x0 = s_x[t][0], x1 = s_x[t][1], x2 = s_x[t][2];

    {
        float dx = x0 - c0, dy = x1 - c1, dz = x2 - c2;
        s_dd[t] = dx * dx + dy * dy + dz * dz;
        unsigned long long key =
            ((unsigned long long)f2ord(s_c[t]) << 32) | (unsigned)(127 - t);
        atomicMax(&s_top1key, key);
    }

    for (int lev = 0; lev < 3; lev++) {
        if (t < 27) { s_add[t] = 0.f; s_cnt[t] = 0.f; }
        __syncthreads();
        float r  = 0.25f * (float)(1 << lev);
        float d0 = rintf((x0 - c0) / r);
        float d1 = rintf((x1 - c1) / r);
        float d2 = rintf((x2 - c2) / r);
        if (fabsf(d0) <= 1.0f && fabsf(d1) <= 1.0f && fabsf(d2) <= 1.0f) {
            int cube = (int)((d0 + 1.f) * 9.f + (d1 + 1.f) * 3.f + (d2 + 1.f));
            atomicAdd(&s_add[cube], s_c[t]);
            atomicAdd(&s_cnt[cube], 1.f);
        }
        __syncthreads();
        if (t < 27)
            g_vfeat[(size_t)(lev * 27 + t) * NPTS + n] = s_add[t] / fmaxf(s_cnt[t], 1.f);
        __syncthreads();
    }

    if (t < 28) s_center[t] = 0ull;
    __syncthreads();
    {
        float d0 = rintf((x0 - c0) / 4.0f);
        float d1 = rintf((x1 - c1) / 4.0f);
        float d2 = rintf((x2 - c2) / 4.0f);
        if (fabsf(d0) <= 1.5f && fabsf(d1) <= 1.5f && fabsf(d2) <= 1.5f) {
            int b = (int)((d0 + 1.f) * 9.f + (d1 + 1.f) * 3.f + (d2 + 1.f)) + 1;
            unsigned long long key =
                ((unsigned long long)f2ord(s_c[t]) << 32) | (unsigned)(127 - t);
            atomicMax(&s_center[b], key);
        }
    }
    __syncthreads();
    int top1 = 127 - (int)(s_top1key & 0xFFFFFFFFu);
    if (t < 27) {
        unsigned long long k = s_center[t + 1];
        int oob, idx;
        if (k == 0ull) { oob = 1; idx = top1; }
        else {
            float v = __uint_as_float(((unsigned)(k >> 32) & 0x80000000u)
                        ? ((unsigned)(k >> 32) & 0x7FFFFFFFu)
                        : ~(unsigned)(k >> 32));
            oob = (v <= 0.f);
            idx = oob ? top1 : (127 - (int)(k & 0xFFFFFFFFu));
        }
        s_oob[t] = oob;
        float cc0 = s_x[idx][0], cc1 = s_x[idx][1], cc2 = s_x[idx][2];
        float bx = (float)((t / 9) % 3 - 1);
        float by = (float)((t / 3) % 3 - 1);
        float bz = (float)(t % 3 - 1);
        float vk0 = c0 + bx * 4.f, vk1 = c1 + by * 4.f, vk2 = c2 + bz * 4.f;
        float m0 = fminf(fmaxf(cc0 - vk0, -1.f), 1.f) + vk0;
        float m1 = fminf(fmaxf(cc1 - vk1, -1.f), 1.f) + vk1;
        float m2 = fminf(fmaxf(cc2 - vk2, -1.f), 1.f) + vk2;
        s_mv[t][0] = m0; s_mv[t][1] = m1; s_mv[t][2] = m2;
        size_t o = ((size_t)n * 27 + t) * 3;
        g_vxyz[o + 0] = m0; g_vxyz[o + 1] = m1; g_vxyz[o + 2] = m2;
    }
    if (t < 28) { s_cadd[t] = 0.f; s_ccnt[t] = 0.f; }
    __syncthreads();

    {
        int idx = 27;
        for (int k = 0; k < 27; k++) {
            if (!s_oob[k]) {
                if (fabsf((x0 - s_mv[k][0]) / 2.0f) <= 0.5f &&
                    fabsf((x1 - s_mv[k][1]) / 2.0f) <= 0.5f &&
                    fabsf((x2 - s_mv[k][2]) / 2.0f) <= 0.5f)
                    idx = k;
            }
        }
        atomicAdd(&s_cadd[idx], s_c[t]);
        atomicAdd(&s_ccnt[idx], 1.f);
    }
    {
        float dd = s_dd[t];
        int r = 0;
#pragma unroll 8
        for (int j = 0; j < KSEL; j++) {
            float dj = s_dd[j];
            r += (dj < dd || (dj == dd && j < t)) ? 1 : 0;
        }
        if (r < KNN) {
            float kc = s_c[t];
            float k0 = x0 - c0, k1 = x1 - c1, k2 = x2 - c2;
            s_kin[r][0] = kc; s_kin[r][1] = k0; s_kin[r][2] = k1; s_kin[r][3] = k2;
            size_t o = ((size_t)n * KNN + r) * 4;
            g_kin[o] = kc; g_kin[o + 1] = k0; g_kin[o + 2] = k1; g_kin[o + 3] = k2;
        }
    }
    __syncthreads();
    if (t < 27) {
        float vc = s_cadd[t] / fmaxf(s_ccnt[t], 1.f);
        s_vcorr[t] = vc;
        g_vcorr[(size_t)n * 27 + t] = vc;
    }
    __syncthreads();

    if (t >= 64 && t < 96) {
        int ch = t - 64;
        float w0 = vw1[ch * 4 + 0], w1_ = vw1[ch * 4 + 1];
        float w2_ = vw1[ch * 4 + 2], w3_ = vw1[ch * 4 + 3];
        float bb = vb1[ch];
        float sum = 0.f, sum2 = 0.f;
#pragma unroll
        for (int k = 0; k < 27; k++) {
            float h = w0 * s_vcorr[k] + w1_ * s_mv[k][0] + w2_ * s_mv[k][1] + w3_ * s_mv[k][2] + bb;
            sum += h; sum2 += h * h;
        }
        sum  += __shfl_xor_sync(0xFFFFFFFFu, sum, 1);
        sum2 += __shfl_xor_sync(0xFFFFFFFFu, sum2, 1);
        sum  += __shfl_xor_sync(0xFFFFFFFFu, sum, 2);
        sum2 += __shfl_xor_sync(0xFFFFFFFFu, sum2, 2);
        if ((ch & 3) == 0) { s_gs[ch >> 2] = sum; s_gs2[ch >> 2] = sum2; }
    }
    if (t < 64) {
        int ch = t;
        float w0 = kw1[ch * 4 + 0], w1_ = kw1[ch * 4 + 1];
        float w2_ = kw1[ch * 4 + 2], w3_ = kw1[ch * 4 + 3];
        float bb = kb1[ch];
        float sum = 0.f, sum2 = 0.f;
#pragma unroll
        for (int s = 0; s < KNN; s++) {
            float h = w0 * s_kin[s][0] + w1_ * s_kin[s][1] + w2_ * s_kin[s][2] + w3_ * s_kin[s][3] + bb;
            sum += h; sum2 += h * h;
        }
        sum  += __shfl_xor_sync(0xFFFFFFFFu, sum, 1);
        sum2 += __shfl_xor_sync(0xFFFFFFFFu, sum2, 1);
        sum  += __shfl_xor_sync(0xFFFFFFFFu, sum, 2);
        sum2 += __shfl_xor_sync(0xFFFFFFFFu, sum2, 2);
        sum  += __shfl_xor_sync(0xFFFFFFFFu, sum, 4);
        sum2 += __shfl_xor_sync(0xFFFFFFFFu, sum2, 4);
        if ((ch & 7) == 0) { s_kgs[ch >> 3] = sum; s_kgs2[ch >> 3] = sum2; }
    }
    __syncthreads();
    if (t < 8) {
        atomicAdd(&g_vox_sum[t],  (double)s_gs[t]);
        atomicAdd(&g_vox_sum2[t], (double)s_gs2[t]);
        atomicAdd(&g_knn_sum[t],  (double)s_kgs[t]);
        atomicAdd(&g_knn_sum2[t], (double)s_kgs2[t]);
    }
}

// ---------------- K4: finalize vox + knn GN stats ----------------
__global__ void finalize_vk_kernel() {
    int t = threadIdx.x;
    if (t < 8) {
        double cnt = 4.0 * NPTS * 27.0;
        double mu  = g_vox_sum[t] / cnt;
        double var = g_vox_sum2[t] / cnt - mu * mu;
        g_vox_mu[t]  = (float)mu;
        g_vox_inv[t] = (float)(1.0 / sqrt(var + 1e-5));
    } else if (t < 16) {
        int g = t - 8;
        double cnt = 8.0 * NPTS * (double)KNN;
        double mu  = g_knn_sum[g] / cnt;
        double var = g_knn_sum2[g] / cnt - mu * mu;
        g_knn_mu[g]  = (float)mu;
        g_knn_inv[g] = (float)(1.0 / sqrt(var + 1e-5));
    }
}

// ---------------- K5: vox MLP apply -> vfeat channels 81..107 ----------------
__global__ void vox_apply_kernel(const float* __restrict__ w1, const float* __restrict__ b1,
                                 const float* __restrict__ gma, const float* __restrict__ bta,
                                 const float* __restrict__ pr, const float* __restrict__ w2,
                                 const float* __restrict__ b2) {
    int idx = blockIdx.x * blockDim.x + threadIdx.x;
    if (idx >= NPTS * 27) return;
    int n = idx / 27, k = idx % 27;
    float vc = g_vcorr[idx];
    float m0 = g_vxyz[(size_t)idx * 3 + 0];
    float m1 = g_vxyz[(size_t)idx * 3 + 1];
    float m2 = g_vxyz[(size_t)idx * 3 + 2];
    float a = pr[0];
    float acc = b2[0];
#pragma unroll
    for (int ch = 0; ch < 32; ch++) {
        float h = w1[ch * 4 + 0] * vc + w1[ch * 4 + 1] * m0
                + w1[ch * 4 + 2] * m1 + w1[ch * 4 + 3] * m2 + b1[ch];
        int gr = ch >> 2;
        h = (h - g_vox_mu[gr]) * g_vox_inv[gr] * gma[ch] + bta[ch];
        h = (h >= 0.f) ? h : a * h;
        acc += w2[ch] * h;
    }
    g_vfeat[(size_t)(81 + k) * NPTS + n] = acc;
}

// ---------------- K6: out conv1 (128 x 108) + GN stats ----------------
__global__ void out_conv1_kernel(const float* __restrict__ w1, const float* __restrict__ b1) {
    __shared__ float vt[108][64];
    int n0 = blockIdx.x * 64;
    int o  = threadIdx.x;  // 128
    for (int i = threadIdx.x; i < 108 * 64; i += 128) {
        int c = i / 64, nn = i % 64;
        vt[c][nn] = g_vfeat[(size_t)c * NPTS + n0 + nn];
    }
    __syncthreads();
    float bo = b1[o];
    float lsf = 0.f, ls2f = 0.f;
    for (int nb = 0; nb < 64; nb += 8) {
        float acc[8];
#pragma unroll
        for (int q = 0; q < 8; q++) acc[q] = bo;
        for (int c = 0; c < 108; c++) {
            float wv = __ldg(&w1[o * 108 + c]);
#pragma unroll
            for (int q = 0; q < 8; q++) acc[q] += wv * vt[c][nb + q];
        }
#pragma unroll
        for (int q = 0; q < 8; q++) {
            g_hout[(size_t)o * NPTS + n0 + nb + q] = acc[q];
            lsf  += acc[q];
            ls2f += acc[q] * acc[q];
        }
    }
    atomicAdd(&g_out_sum[o >> 4],  (double)lsf);
    atomicAdd(&g_out_sum2[o >> 4], (double)ls2f);
}

// ---------------- K7: finalize out GN stats ----------------
__global__ void finalize_out_kernel() {
    int t = threadIdx.x;
    if (t < 8) {
        double cnt = 16.0 * NPTS;
        double mu  = g_out_sum[t] / cnt;
        double var = g_out_sum2[t] / cnt - mu * mu;
        g_out_mu[t]  = (float)mu;
        g_out_inv[t] = (float)(1.0 / sqrt(var + 1e-5));
    }
}

// ---------------- K8: out GN+prelu + conv2 (64 x 128) -> d_out ----------------
__global__ void out_apply_kernel(const float* __restrict__ gma, const float* __restrict__ bta,
                                 const float* __restrict__ pr, const float* __restrict__ w2,
                                 const float* __restrict__ b2, float* __restrict__ out) {
    __shared__ float act[128][64];
    int n0 = blockIdx.x * 64;
    int t  = threadIdx.x;  // 256
    float a = pr[0];
    for (int i = t; i < 128 * 64; i += 256) {
        int ch = i / 64, nn = i % 64;
        float x = g_hout[(size_t)ch * NPTS + n0 + nn];
        int gr = ch >> 4;
        x = (x - g_out_mu[gr]) * g_out_inv[gr] * gma[ch] + bta[ch];
        act[ch][nn] = (x >= 0.f) ? x : a * x;
    }
    __syncthreads();
    for (int i = t; i < 64 * 64; i += 256) {
        int o = i / 64, nn = i % 64;
        float acc = b2[o];
        for (int c = 0; c < 128; c++) acc += w2[o * 128 + c] * act[c][nn];
        out[(size_t)o * NPTS + n0 + nn] = acc;
    }
}

// ---------------- K9: knn GN+prelu+max + conv (64x64), add into d_out ----------
__global__ void knn_apply_kernel(const float* __restrict__ w1, const float* __restrict__ b1,
                                 const float* __restrict__ gma, const float* __restrict__ bta,
                                 const float* __restrict__ pr, const float* __restrict__ ow,
                                 const float* __restrict__ ob, float* __restrict__ out) {
    __shared__ float s_kf[64];
    __shared__ float s_kin[KNN][4];
    int n = blockIdx.x;
    int t = threadIdx.x;  // 64
    for (int i = t; i < KNN * 4; i += 64)
        s_kin[i / 4][i % 4] = g_kin[(size_t)n * KNN * 4 + i];
    __syncthreads();
    {
        int ch = t;
        float a = pr[0];
        float w0 = w1[ch * 4 + 0], w1_ = w1[ch * 4 + 1], w2_ = w1[ch * 4 + 2], w3_ = w1[ch * 4 + 3];
        float bb = b1[ch];
        float mu = g_knn_mu[ch >> 3], inv = g_knn_inv[ch >> 3];
        float gg = gma[ch], bt_ = bta[ch];
        float mx = -INFINITY;
#pragma unroll
        for (int s = 0; s < KNN; s++) {
            float h = w0 * s_kin[s][0] + w1_ * s_kin[s][1] + w2_ * s_kin[s][2] + w3_ * s_kin[s][3] + bb;
            h = (h - mu) * inv * gg + bt_;
            h = (h >= 0.f) ? h : a * h;
            mx = fmaxf(mx, h);
        }
        s_kf[ch] = mx;
    }
    __syncthreads();
    {
        int o = t;
        float acc = ob[o];
#pragma unroll
        for (int c = 0; c < 64; c++) acc += ow[o * 64 + c] * s_kf[c];
        out[(size_t)o * NPTS + n] += acc;
    }
}

// ---------------- launch ----------------
extern "C" void kernel_launch(void* const* d_in, const int* in_sizes, int n_in,
                              void* d_out, int out_size) {
    const float* fmap1  = (const float*)d_in[0];
    const float* fmap2  = (const float*)d_in[1];
    const float* xyz2   = (const float*)d_in[2];
    const float* coords = (const float*)d_in[3];
    const float* out_w1 = (const float*)d_in[4];
    const float* out_b1 = (const float*)d_in[5];
    const float* out_g  = (const float*)d_in[6];
    const float* out_bt = (const float*)d_in[7];
    const float* out_pr = (const float*)d_in[8];
    const float* out_w2 = (const float*)d_in[9];
    const float* out_b2 = (const float*)d_in[10];
    const float* vox_w1 = (const float*)d_in[11];
    const float* vox_b1 = (const float*)d_in[12];
    const float* vox_g  = (const float*)d_in[13];
    const float* vox_bt = (const float*)d_in[14];
    const float* vox_pr = (const float*)d_in[15];
    const float* vox_w2 = (const float*)d_in[16];
    const float* vox_b2 = (const float*)d_in[17];
    const float* knn_w1 = (const float*)d_in[18];
    const float* knn_b1 = (const float*)d_in[19];
    const float* knn_g  = (const float*)d_in[20];
    const float* knn_bt = (const float*)d_in[21];
    const float* knn_pr = (const float*)d_in[22];
    const float* knn_ow = (const float*)d_in[23];
    const float* knn_ob = (const float*)d_in[24];
    float* out = (float*)d_out;

    cudaFuncSetAttribute(gemm_mma_kernel, cudaFuncAttributeMaxDynamicSharedMemorySize,
                         SM_GEMM_TOTAL);

    prep_kernel<<<dim3(NPTS / 64, 2), 256>>>(fmap1, fmap2);
    gemm_mma_kernel<<<dim3(NPTS / 128, NPTS / 128), 256, SM_GEMM_TOTAL>>>();
    topk_kernel<<<NPTS, 256>>>(xyz2);
    pointfeat_kernel<<<NPTS, 128>>>(coords, vox_w1, vox_b1, knn_w1, knn_b1);
    finalize_vk_kernel<<<1, 32>>>();
    vox_apply_kernel<<<(NPTS * 27 + 255) / 256, 256>>>(vox_w1, vox_b1, vox_g, vox_bt,
                                                       vox_pr, vox_w2, vox_b2);
    out_conv1_kernel<<<NPTS / 64, 128>>>(out_w1, out_b1);
    finalize_out_kernel<<<1, 32>>>();
    out_apply_kernel<<<NPTS / 64, 256>>>(out_g, out_bt, out_pr, out_w2, out_b2, out);
    knn_apply_kernel<<<NPTS, 64>>>(knn_w1, knn_b1, knn_g, knn_bt, knn_pr,
                                   knn_ow, knn_ob, out);
}

// round 13
// speedup vs baseline: 1.6308x; 1.2161x over previous
#include <cuda_runtime.h>
#include <cuda_bf16.h>
#include <math.h>
#include <stdint.h>

#define NPTS 8192
#define CCH  128
#define KSEL 128
#define KNN  32
#define KCAND 192      // approximate preselection size (slack 64 over KSEL)
#define CAND_CAP 768

// ---------------- scratch (device globals; no allocation) ----------------
__device__ __nv_bfloat16 g_corrh[(size_t)NPTS * NPTS]; // 128 MB approx corr
__device__ __nv_bfloat16 g_f1hi[(size_t)NPTS * CCH];   // [n][k] bf16
__device__ __nv_bfloat16 g_f2hi[(size_t)NPTS * CCH];
__device__ float  g_f1t[(size_t)NPTS * CCH];           // [n][k] fp32 (exact re-rank)
__device__ float  g_f2t[(size_t)NPTS * CCH];
__device__ float  g_tcorr[NPTS * KSEL];
__device__ float  g_txyz[NPTS * KSEL * 3];
__device__ float  g_vfeat[108 * NPTS];
__device__ float  g_vcorr[NPTS * 27];
__device__ float  g_vxyz[NPTS * 27 * 3];
__device__ float  g_kin[NPTS * KNN * 4];
__device__ float  g_hout[128 * NPTS];

__device__ double g_vox_sum[8],  g_vox_sum2[8];
__device__ double g_knn_sum[8],  g_knn_sum2[8];
__device__ double g_out_sum[8],  g_out_sum2[8];
__device__ float  g_vox_mu[8], g_vox_inv[8];
__device__ float  g_knn_mu[8], g_knn_inv[8];
__device__ float  g_out_mu[8], g_out_inv[8];

// ---------------- helpers ----------------
__device__ __forceinline__ unsigned f2ord(float f) {
    unsigned u = __float_as_uint(f);
    return (u & 0x80000000u) ? ~u : (u | 0x80000000u);
}
__device__ __forceinline__ uint32_t smem_u32(const void* p) {
    uint32_t a;
    asm("{ .reg .u64 t; cvta.to.shared.u64 t, %1; cvt.u32.u64 %0, t; }" : "=r"(a) : "l"(p));
    return a;
}

// ---------------- Kp: transpose; write fp32 [n][k] + bf16 hi [n][k]; zero stats --
__global__ __launch_bounds__(256) void prep_kernel(const float* __restrict__ f1,
                                                   const float* __restrict__ f2) {
    __shared__ float tile[128][65];
    if (blockIdx.x == 0 && blockIdx.y == 0 && threadIdx.x < 8) {
        int q = threadIdx.x;
        g_vox_sum[q] = 0.0; g_vox_sum2[q] = 0.0;
        g_knn_sum[q] = 0.0; g_knn_sum2[q] = 0.0;
        g_out_sum[q] = 0.0; g_out_sum2[q] = 0.0;
    }
    const float* src = blockIdx.y ? f2 : f1;
    __nv_bfloat16* dhi = blockIdx.y ? g_f2hi : g_f1hi;
    float* dt = blockIdx.y ? g_f2t : g_f1t;
    int n0 = blockIdx.x * 64;
    int t = threadIdx.x;
    for (int i = t; i < 128 * 64; i += 256) {
        int n = i & 63;
        int k = i >> 6;
        tile[k][n] = src[(size_t)k * NPTS + n0 + n];
    }
    __syncthreads();
    for (int i = t; i < 64 * 128; i += 256) {
        int k = i & 127;
        int n = i >> 7;
        float v = tile[k][n];
        dt[(size_t)(n0 + n) * CCH + k]  = v;
        dhi[(size_t)(n0 + n) * CCH + k] = __float2bfloat16(v);
    }
}

// ---------------- K1: bf16 GEMM via mma.sync (HMMA), 128x128 per CTA, bf16 out --
#define TILE_BYTES 32768
#define SM_AHI 0
#define SM_BHI (SM_AHI + TILE_BYTES)
#define SM_GEMM_TOTAL (2 * TILE_BYTES)
#define SOUT 136   // bf16 elements per staged output row (272 B)

__device__ __forceinline__ uint32_t swz_off(int row, int chunk) {
    return (uint32_t)(row * 256 + ((chunk ^ (row & 7)) << 4));
}

__global__ __launch_bounds__(256) void gemm_mma_kernel() {
    extern __shared__ char smem[];
    uint32_t sbase = smem_u32(smem);
    int t = threadIdx.x;        // 256
    int bm = blockIdx.y * 128;
    int bn = blockIdx.x * 128;

#pragma unroll 1
    for (int tl = 0; tl < 2; tl++) {
        const __nv_bfloat16* sp = tl ? g_f2hi : g_f1hi;
        int srow = tl ? bn : bm;
        int soff = tl ? SM_BHI : SM_AHI;
        const uint4* src = (const uint4*)(sp + (size_t)srow * CCH);
#pragma unroll
        for (int it = 0; it < 8; it++) {
            int i   = t + it * 256;     // 0..2047
            int row = i >> 4;
            int chk = i & 15;
            uint4 v = src[(size_t)row * 16 + chk];
            *(uint4*)(smem + soff + swz_off(row, chk)) = v;
        }
    }
    __syncthreads();

    int wid  = t >> 5;
    int lane = t & 31;
    int wm = wid & 3;
    int wn = wid >> 2;
    int lrow = lane & 7;
    int lblk = lane >> 3;

    float acc[2][8][4];
#pragma unroll
    for (int i = 0; i < 2; i++)
#pragma unroll
        for (int j = 0; j < 8; j++)
#pragma unroll
            for (int q = 0; q < 4; q++) acc[i][j][q] = 0.f;

    uint32_t abase = sbase + SM_AHI;
    uint32_t bbase = sbase + SM_BHI;
#pragma unroll 1
    for (int ks = 0; ks < 8; ks++) {
        uint32_t a[2][4];
#pragma unroll
        for (int i = 0; i < 2; i++) {
            int row = wm * 32 + i * 16 + lrow + (lblk & 1) * 8;
            int chk = ks * 2 + (lblk >> 1);
            uint32_t addr = abase + swz_off(row, chk);
            asm volatile("ldmatrix.sync.aligned.m8n8.x4.shared.b16 {%0,%1,%2,%3}, [%4];"
                         : "=r"(a[i][0]), "=r"(a[i][1]), "=r"(a[i][2]), "=r"(a[i][3])
                         : "r"(addr));
        }
        uint32_t b[8][2];
#pragma unroll
        for (int jj = 0; jj < 4; jj++) {
            int row = wn * 64 + (jj * 2 + (lblk >> 1)) * 8 + lrow;
            int chk = ks * 2 + (lblk & 1);
            uint32_t addr = bbase + swz_off(row, chk);
            uint32_t r0, r1, r2, r3;
            asm volatile("ldmatrix.sync.aligned.m8n8.x4.shared.b16 {%0,%1,%2,%3}, [%4];"
                         : "=r"(r0), "=r"(r1), "=r"(r2), "=r"(r3)
                         : "r"(addr));
            b[jj * 2][0] = r0; b[jj * 2][1] = r1;
            b[jj * 2 + 1][0] = r2; b[jj * 2 + 1][1] = r3;
        }
#pragma unroll
        for (int i = 0; i < 2; i++)
#pragma unroll
            for (int j = 0; j < 8; j++) {
                asm volatile(
                    "mma.sync.aligned.m16n8k16.row.col.f32.bf16.bf16.f32 "
                    "{%0,%1,%2,%3}, {%4,%5,%6,%7}, {%8,%9}, {%0,%1,%2,%3};"
                    : "+f"(acc[i][j][0]), "+f"(acc[i][j][1]),
                      "+f"(acc[i][j][2]), "+f"(acc[i][j][3])
                    : "r"(a[i][0]), "r"(a[i][1]), "r"(a[i][2]), "r"(a[i][3]),
                      "r"(b[j][0]), "r"(b[j][1]));
            }
    }

    // ---- epilogue: stage into smem, then coalesced 256B rows ----
    __syncthreads();
    __nv_bfloat16* stile = (__nv_bfloat16*)smem;
    const float scale = 0.088388347648318447f;  // 1/sqrt(128)
#pragma unroll
    for (int i = 0; i < 2; i++) {
        int row0 = wm * 32 + i * 16 + (lane >> 2);
#pragma unroll
        for (int j = 0; j < 8; j++) {
            int col = wn * 64 + j * 8 + ((lane & 3) << 1);
            float2 v0, v1;
            v0.x = acc[i][j][0] * scale; v0.y = acc[i][j][1] * scale;
            v1.x = acc[i][j][2] * scale; v1.y = acc[i][j][3] * scale;
            *(__nv_bfloat162*)&stile[row0 * SOUT + col]       = __float22bfloat162_rn(v0);
            *(__nv_bfloat162*)&stile[(row0 + 8) * SOUT + col] = __float22bfloat162_rn(v1);
        }
    }
    __syncthreads();
#pragma unroll
    for (int it = 0; it < 8; it++) {
        int idx = t + it * 256;     // 0..2047
        int row = idx >> 4;
        int seg = idx & 15;
        uint4 v = *(const uint4*)&stile[row * SOUT + seg * 8];
        *(uint4*)&g_corrh[(size_t)(bm + row) * NPTS + bn + seg * 8] = v;
    }
}

// ---------------- K2: fused preselect (12-bit + 4-bit refine) + exact re-rank ---
__global__ __launch_bounds__(256) void topk_kernel(const float* __restrict__ xyz2) {
    __shared__ unsigned s_key2[NPTS / 2];        // 16 KB packed ord16 pairs
    __shared__ unsigned s_hist[4096];            // 16 KB (12-bit bins)
    __shared__ unsigned s_gsum[256];             // 1 KB (group = 16 bins)
    __shared__ unsigned s_h16[16];
    __shared__ float    s_f1[CCH];               // 0.5 KB
    __shared__ unsigned s_cidx[CAND_CAP];        // 3 KB
    __shared__ float    s_val[CAND_CAP];         // 3 KB
    __shared__ unsigned long long s_pk[CAND_CAP];// 6 KB
    __shared__ unsigned s_crossg, s_cumabove, s_bin12, s_cum12, s_thr, s_ccnt;

    int n = blockIdx.x;
    int t = threadIdx.x;  // 256

    for (int i = t; i < 4096; i += 256) s_hist[i] = 0;
    if (t < 128) s_f1[t] = g_f1t[(size_t)n * CCH + t];
    if (t == 0) s_ccnt = 0;
    if (t >= 240) s_h16[t - 240] = 0;
    __syncthreads();

    // pass A: load bf16 row, SIMD ord16 (both halves at once), 12-bit hist
    const uint4* rowp = (const uint4*)(g_corrh + (size_t)n * NPTS);
    for (int i = t; i < NPTS / 8; i += 256) {
        uint4 v = rowp[i];
        unsigned w[4] = {v.x, v.y, v.z, v.w};
#pragma unroll
        for (int q = 0; q < 4; q++) {
            unsigned vv = w[q];
            unsigned mask = (((vv >> 15) & 0x00010001u) * 0x7FFFu) | 0x80008000u;
            unsigned key2 = vv ^ mask;
            s_key2[i * 4 + q] = key2;
            atomicAdd(&s_hist[(key2 >> 4) & 0xFFFu], 1u);
            atomicAdd(&s_hist[key2 >> 20], 1u);
        }
    }
    __syncthreads();
    // group sums (16 bins each)
    {
        unsigned sum = 0;
#pragma unroll
        for (int b = 0; b < 16; b++) sum += s_hist[t * 16 + b];
        s_gsum[t] = sum;
    }
    __syncthreads();
    // warp 0: find crossing group via suffix scan (descending key order)
    if (t < 32) {
        int lane = t;
        int gtop = 255 - lane * 8;   // lane 0 owns the TOP 8 groups
        unsigned local = 0;
#pragma unroll
        for (int q = 0; q < 8; q++) local += s_gsum[gtop - q];
        unsigned pre = local;
#pragma unroll
        for (int d = 1; d < 32; d <<= 1) {
            unsigned other = __shfl_up_sync(0xFFFFFFFFu, pre, d);
            if (lane >= d) pre += other;
        }
        unsigned run = pre - local;  // count strictly above this lane's block
#pragma unroll
        for (int q = 0; q < 8; q++) {
            int g = gtop - q;
            unsigned c = s_gsum[g];
            if (run < KCAND && run + c >= KCAND) { s_crossg = (unsigned)g; s_cumabove = run; }
            run += c;
        }
    }
    __syncthreads();
    if (t == 0) {
        unsigned g = s_crossg;
        unsigned cum = s_cumabove;
        unsigned bin = g * 16;
        for (int b = 15; b >= 0; b--) {
            unsigned h = s_hist[g * 16 + b];
            if (cum + h >= KCAND) { bin = g * 16 + (unsigned)b; break; }
            cum += h;
        }
        s_bin12 = bin;
        s_cum12 = cum;
    }
    __syncthreads();
    // pass B: 4-bit refinement within the crossing 12-bit bin
    unsigned bin12 = s_bin12;
    for (int i = t; i < NPTS / 2; i += 256) {
        unsigned kk = s_key2[i];
        if (((kk >> 4) & 0xFFFu) == bin12) atomicAdd(&s_h16[kk & 0xFu], 1u);
        if ((kk >> 20) == bin12)           atomicAdd(&s_h16[(kk >> 16) & 0xFu], 1u);
    }
    __syncthreads();
    if (t == 0) {
        unsigned cum = s_cum12;
        unsigned thr = bin12 << 4;
        for (int b = 15; b >= 0; b--) {
            unsigned h = s_h16[b];
            if (cum + h >= KCAND) { thr = (bin12 << 4) | (unsigned)b; break; }
            cum += h;
        }
        s_thr = thr;
    }
    __syncthreads();
    unsigned thr = s_thr;
    // pass C: compact candidate indices (key >= thr) into smem
    for (int i = t; i < NPTS / 2; i += 256) {
        unsigned kk = s_key2[i];
        if ((kk & 0xFFFFu) >= thr) {
            unsigned ci = atomicAdd(&s_ccnt, 1u);
            if (ci < CAND_CAP) s_cidx[ci] = (unsigned)(i * 2);
        }
        if ((kk >> 16) >= thr) {
            unsigned ci = atomicAdd(&s_ccnt, 1u);
            if (ci < CAND_CAP) s_cidx[ci] = (unsigned)(i * 2 + 1);
        }
    }
    __syncthreads();
    unsigned C = min(s_ccnt, (unsigned)CAND_CAP);

    // exact fp32 dots: 4 candidates per warp, 8-lane groups, 3-shfl reduce
    {
        int wid = t >> 5, lane = t & 31;
        int grp = lane >> 3, gl = lane & 7;
        const float4* f1v = (const float4*)s_f1;
        float4 a0 = f1v[gl];
        float4 a1 = f1v[gl + 8];
        float4 a2 = f1v[gl + 16];
        float4 a3 = f1v[gl + 24];
        const float scale = 0.088388347648318447f;
        for (unsigned cb = (unsigned)wid * 4; cb < C; cb += 32) {
            unsigned c = cb + (unsigned)grp;
            unsigned m = s_cidx[(c < C) ? c : 0];
            const float4* f2 = (const float4*)(g_f2t + (size_t)m * CCH);
            float4 b0 = f2[gl], b1 = f2[gl + 8], b2 = f2[gl + 16], b3 = f2[gl + 24];
            float p = a0.x * b0.x + a0.y * b0.y + a0.z * b0.z + a0.w * b0.w
                    + a1.x * b1.x + a1.y * b1.y + a1.z * b1.z + a1.w * b1.w
                    + a2.x * b2.x + a2.y * b2.y + a2.z * b2.z + a2.w * b2.w
                    + a3.x * b3.x + a3.y * b3.y + a3.z * b3.z + a3.w * b3.w;
            p += __shfl_xor_sync(0xFFFFFFFFu, p, 4);
            p += __shfl_xor_sync(0xFFFFFFFFu, p, 2);
            p += __shfl_xor_sync(0xFFFFFFFFu, p, 1);
            if (gl == 0 && c < C) s_val[c] = p * scale;
        }
    }
    __syncthreads();
    // packed rank keys: value desc, index asc
    for (unsigned c = t; c < C; c += 256)
        s_pk[c] = ((unsigned long long)f2ord(s_val[c]) << 32)
                | (unsigned long long)(8191u - s_cidx[c]);
    __syncthreads();

    for (unsigned c = t; c < C; c += 256) {
        unsigned long long kc = s_pk[c];
        unsigned r = 0;
        for (unsigned j = 0; j < C; j++) r += (s_pk[j] > kc) ? 1u : 0u;
        if (r < KSEL) {
            unsigned mc = s_cidx[c];
            g_tcorr[(size_t)n * KSEL + r] = s_val[c];
            size_t o = ((size_t)n * KSEL + r) * 3;
            g_txyz[o + 0] = xyz2[(size_t)mc * 3 + 0];
            g_txyz[o + 1] = xyz2[(size_t)mc * 3 + 1];
            g_txyz[o + 2] = xyz2[(size_t)mc * 3 + 2];
        }
    }
}

// ---------------- K3: per-point voxel levels + coarse stage + knn select + GN stats
__global__ __launch_bounds__(128) void pointfeat_kernel(const float* __restrict__ coords,
                                 const float* __restrict__ vw1, const float* __restrict__ vb1,
                                 const float* __restrict__ kw1, const float* __restrict__ kb1) {
    __shared__ float s_c[KSEL];
    __shared__ float s_x[KSEL][3];
    __shared__ float s_dd[KSEL];
    __shared__ float s_coord[3];
    __shared__ float s_add[81], s_cnt[81];
    __shared__ unsigned long long s_center[28];
    __shared__ float s_mv[27][3];
    __shared__ int   s_oob[27];
    __shared__ float s_cadd[28], s_ccnt[28];
    __shared__ float s_vcorr[27];
    __shared__ float s_kin[KNN][4];
    __shared__ float s_gs[8], s_gs2[8], s_kgs[8], s_kgs2[8];
    __shared__ unsigned long long s_top1key;

    int n = blockIdx.x;
    int t = threadIdx.x;  // 128

    s_c[t] = g_tcorr[(size_t)n * KSEL + t];
    {
        size_t o = ((size_t)n * KSEL + t) * 3;
        s_x[t][0] = g_txyz[o + 0];
        s_x[t][1] = g_txyz[o + 1];
        s_x[t][2] = g_txyz[o + 2];
    }
    if (t < 3) s_coord[t] = coords[(size_t)n * 3 + t];
    if (t < 81) { s_add[t] = 0.f; s_cnt[t] = 0.f; }
    if (t < 28) { s_center[t] = 0ull; s_cadd[t] = 0.f; s_ccnt[t] = 0.f; }
    if (t == 0) s_top1key = 0ull;
    __syncthreads();   // [1]

    float c0 = s_coord[0], c1 = s_coord[1], c2 = s_coord[2];
    float x0 = s_x[t][0], x1 = s_x[t][1], x2 = s_x[t][2];
    float dx = x0 - c0, dy = x1 - c1, dz = x2 - c2;
    s_dd[t] = dx * dx + dy * dy + dz * dz;
    {
        unsigned long long key =
            ((unsigned long long)f2ord(s_c[t]) << 32) | (unsigned)(127 - t);
        atomicMax(&s_top1key, key);
        // 3 avg-pool levels into 81 bins
#pragma unroll
        for (int lev = 0; lev < 3; lev++) {
            float r  = 0.25f * (float)(1 << lev);
            float d0 = rintf(dx / r);
            float d1 = rintf(dy / r);
            float d2 = rintf(dz / r);
            if (fabsf(d0) <= 1.0f && fabsf(d1) <= 1.0f && fabsf(d2) <= 1.0f) {
                int cube = lev * 27 + (int)((d0 + 1.f) * 9.f + (d1 + 1.f) * 3.f + (d2 + 1.f));
                atomicAdd(&s_add[cube], s_c[t]);
                atomicAdd(&s_cnt[cube], 1.f);
            }
        }
        // coarse scatter-max (R = 4)
        float d0 = rintf(dx / 4.0f);
        float d1 = rintf(dy / 4.0f);
        float d2 = rintf(dz / 4.0f);
        if (fabsf(d0) <= 1.5f && fabsf(d1) <= 1.5f && fabsf(d2) <= 1.5f) {
            int b = (int)((d0 + 1.f) * 9.f + (d1 + 1.f) * 3.f + (d2 + 1.f)) + 1;
            atomicMax(&s_center[b], key);
        }
    }
    __syncthreads();   // [2]

    if (t < 81)
        g_vfeat[(size_t)t * NPTS + n] = s_add[t] / fmaxf(s_cnt[t], 1.f);
    int top1 = 127 - (int)(s_top1key & 0xFFFFFFFFu);
    if (t < 27) {
        unsigned long long k = s_center[t + 1];
        int oob, idx;
        if (k == 0ull) { oob = 1; idx = top1; }
        else {
            float v = __uint_as_float(((unsigned)(k >> 32) & 0x80000000u)
                        ? ((unsigned)(k >> 32) & 0x7FFFFFFFu)
                        : ~(unsigned)(k >> 32));
            oob = (v <= 0.f);
            idx = oob ? top1 : (127 - (int)(k & 0xFFFFFFFFu));
        }
        s_oob[t] = oob;
        float cc0 = s_x[idx][0], cc1 = s_x[idx][1], cc2 = s_x[idx][2];
        float bx = (float)((t / 9) % 3 - 1);
        float by = (float)((t / 3) % 3 - 1);
        float bz = (float)(t % 3 - 1);
        float vk0 = c0 + bx * 4.f, vk1 = c1 + by * 4.f, vk2 = c2 + bz * 4.f;
        float m0 = fminf(fmaxf(cc0 - vk0, -1.f), 1.f) + vk0;
        float m1 = fminf(fmaxf(cc1 - vk1, -1.f), 1.f) + vk1;
        float m2 = fminf(fmaxf(cc2 - vk2, -1.f), 1.f) + vk2;
        s_mv[t][0] = m0; s_mv[t][1] = m1; s_mv[t][2] = m2;
        size_t o = ((size_t)n * 27 + t) * 3;
        g_vxyz[o + 0] = m0; g_vxyz[o + 1] = m1; g_vxyz[o + 2] = m2;
    }
    __syncthreads();   // [3]

    // idx_scatter + knn rank-select
    {
        int idx = 27;
        for (int k = 0; k < 27; k++) {
            if (!s_oob[k]) {
                if (fabsf((x0 - s_mv[k][0]) / 2.0f) <= 0.5f &&
                    fabsf((x1 - s_mv[k][1]) / 2.0f) <= 0.5f &&
                    fabsf((x2 - s_mv[k][2]) / 2.0f) <= 0.5f)
                    idx = k;
            }
        }
        atomicAdd(&s_cadd[idx], s_c[t]);
        atomicAdd(&s_ccnt[idx], 1.f);
    }
    {
        float dd = s_dd[t];
        int r = 0;
#pragma unroll 8
        for (int j = 0; j < KSEL; j++) {
            float dj = s_dd[j];
            r += (dj < dd || (dj == dd && j < t)) ? 1 : 0;
        }
        if (r < KNN) {
            float kc = s_c[t];
            s_kin[r][0] = kc; s_kin[r][1] = dx; s_kin[r][2] = dy; s_kin[r][3] = dz;
            size_t o = ((size_t)n * KNN + r) * 4;
            g_kin[o] = kc; g_kin[o + 1] = dx; g_kin[o + 2] = dy; g_kin[o + 3] = dz;
        }
    }
    __syncthreads();   // [4]

    if (t < 27) {
        float vc = s_cadd[t] / fmaxf(s_ccnt[t], 1.f);
        s_vcorr[t] = vc;
        g_vcorr[(size_t)n * 27 + t] = vc;
    }
    __syncthreads();   // [5]

    if (t >= 64 && t < 96) {
        int ch = t - 64;
        float w0 = vw1[ch * 4 + 0], w1_ = vw1[ch * 4 + 1];
        float w2_ = vw1[ch * 4 + 2], w3_ = vw1[ch * 4 + 3];
        float bb = vb1[ch];
        float sum = 0.f, sum2 = 0.f;
#pragma unroll
        for (int k = 0; k < 27; k++) {
            float h = w0 * s_vcorr[k] + w1_ * s_mv[k][0] + w2_ * s_mv[k][1] + w3_ * s_mv[k][2] + bb;
            sum += h; sum2 += h * h;
        }
        sum  += __shfl_xor_sync(0xFFFFFFFFu, sum, 1);
        sum2 += __shfl_xor_sync(0xFFFFFFFFu, sum2, 1);
        sum  += __shfl_xor_sync(0xFFFFFFFFu, sum, 2);
        sum2 += __shfl_xor_sync(0xFFFFFFFFu, sum2, 2);
        if ((ch & 3) == 0) { s_gs[ch >> 2] = sum; s_gs2[ch >> 2] = sum2; }
    }
    if (t < 64) {
        int ch = t;
        float w0 = kw1[ch * 4 + 0], w1_ = kw1[ch * 4 + 1];
        float w2_ = kw1[ch * 4 + 2], w3_ = kw1[ch * 4 + 3];
        float bb = kb1[ch];
        float sum = 0.f, sum2 = 0.f;
#pragma unroll
        for (int s = 0; s < KNN; s++) {
            float h = w0 * s_kin[s][0] + w1_ * s_kin[s][1] + w2_ * s_kin[s][2] + w3_ * s_kin[s][3] + bb;
            sum += h; sum2 += h * h;
        }
        sum  += __shfl_xor_sync(0xFFFFFFFFu, sum, 1);
        sum2 += __shfl_xor_sync(0xFFFFFFFFu, sum2, 1);
        sum  += __shfl_xor_sync(0xFFFFFFFFu, sum, 2);
        sum2 += __shfl_xor_sync(0xFFFFFFFFu, sum2, 2);
        sum  += __shfl_xor_sync(0xFFFFFFFFu, sum, 4);
        sum2 += __shfl_xor_sync(0xFFFFFFFFu, sum2, 4);
        if ((ch & 7) == 0) { s_kgs[ch >> 3] = sum; s_kgs2[ch >> 3] = sum2; }
    }
    __syncthreads();   // [6]
    if (t < 8) {
        atomicAdd(&g_vox_sum[t],  (double)s_gs[t]);
        atomicAdd(&g_vox_sum2[t], (double)s_gs2[t]);
        atomicAdd(&g_knn_sum[t],  (double)s_kgs[t]);
        atomicAdd(&g_knn_sum2[t], (double)s_kgs2[t]);
    }
}

// ---------------- K4: finalize vox + knn GN stats ----------------
__global__ void finalize_vk_kernel() {
    int t = threadIdx.x;
    if (t < 8) {
        double cnt = 4.0 * NPTS * 27.0;
        double mu  = g_vox_sum[t] / cnt;
        double var = g_vox_sum2[t] / cnt - mu * mu;
        g_vox_mu[t]  = (float)mu;
        g_vox_inv[t] = (float)(1.0 / sqrt(var + 1e-5));
    } else if (t < 16) {
        int g = t - 8;
        double cnt = 8.0 * NPTS * (double)KNN;
        double mu  = g_knn_sum[g] / cnt;
        double var = g_knn_sum2[g] / cnt - mu * mu;
        g_knn_mu[g]  = (float)mu;
        g_knn_inv[g] = (float)(1.0 / sqrt(var + 1e-5));
    }
}

// ---------------- K5: vox MLP apply -> vfeat channels 81..107 ----------------
__global__ void vox_apply_kernel(const float* __restrict__ w1, const float* __restrict__ b1,
                                 const float* __restrict__ gma, const float* __restrict__ bta,
                                 const float* __restrict__ pr, const float* __restrict__ w2,
                                 const float* __restrict__ b2) {
    int idx = blockIdx.x * blockDim.x + threadIdx.x;
    if (idx >= NPTS * 27) return;
    int n = idx / 27, k = idx % 27;
    float vc = g_vcorr[idx];
    float m0 = g_vxyz[(size_t)idx * 3 + 0];
    float m1 = g_vxyz[(size_t)idx * 3 + 1];
    float m2 = g_vxyz[(size_t)idx * 3 + 2];
    float a = pr[0];
    float acc = b2[0];
#pragma unroll
    for (int ch = 0; ch < 32; ch++) {
        float h = w1[ch * 4 + 0] * vc + w1[ch * 4 + 1] * m0
                + w1[ch * 4 + 2] * m1 + w1[ch * 4 + 3] * m2 + b1[ch];
        int gr = ch >> 2;
        h = (h - g_vox_mu[gr]) * g_vox_inv[gr] * gma[ch] + bta[ch];
        h = (h >= 0.f) ? h : a * h;
        acc += w2[ch] * h;
    }
    g_vfeat[(size_t)(81 + k) * NPTS + n] = acc;
}

// ---------------- K6: out conv1 (128 x 108) + GN stats, 32-pt tiles ------------
__global__ __launch_bounds__(128) void out_conv1_kernel(const float* __restrict__ w1,
                                                        const float* __restrict__ b1) {
    __shared__ float vt[108][32];
    int n0 = blockIdx.x * 32;
    int o  = threadIdx.x;  // 128
    for (int i = threadIdx.x; i < 108 * 32; i += 128) {
        int c = i / 32, nn = i % 32;
        vt[c][nn] = g_vfeat[(size_t)c * NPTS + n0 + nn];
    }
    __syncthreads();
    float bo = b1[o];
    float lsf = 0.f, ls2f = 0.f;
    for (int nb = 0; nb < 32; nb += 8) {
        float acc[8];
#pragma unroll
        for (int q = 0; q < 8; q++) acc[q] = bo;
        for (int c = 0; c < 108; c++) {
            float wv = __ldg(&w1[o * 108 + c]);
#pragma unroll
            for (int q = 0; q < 8; q++) acc[q] += wv * vt[c][nb + q];
        }
#pragma unroll
        for (int q = 0; q < 8; q++) {
            g_hout[(size_t)o * NPTS + n0 + nb + q] = acc[q];
            lsf  += acc[q];
            ls2f += acc[q] * acc[q];
        }
    }
    atomicAdd(&g_out_sum[o >> 4],  (double)lsf);
    atomicAdd(&g_out_sum2[o >> 4], (double)ls2f);
}

// ---------------- K7: finalize out GN stats ----------------
__global__ void finalize_out_kernel() {
    int t = threadIdx.x;
    if (t < 8) {
        double cnt = 16.0 * NPTS;
        double mu  = g_out_sum[t] / cnt;
        double var = g_out_sum2[t] / cnt - mu * mu;
        g_out_mu[t]  = (float)mu;
        g_out_inv[t] = (float)(1.0 / sqrt(var + 1e-5));
    }
}

// ---------------- K8: fused out GN+prelu+conv2 + knn branch -> d_out -----------
#define OA_PTS 32
__global__ __launch_bounds__(256) void out_apply_kernel(
    const float* __restrict__ gma, const float* __restrict__ bta,
    const float* __restrict__ pr,  const float* __restrict__ w2,
    const float* __restrict__ b2,
    const float* __restrict__ kw1, const float* __restrict__ kb1,
    const float* __restrict__ kgma, const float* __restrict__ kbta,
    const float* __restrict__ kpr, const float* __restrict__ kow,
    const float* __restrict__ kob, float* __restrict__ out) {
    __shared__ float act[128][OA_PTS];        // 16 KB
    __shared__ float kin[OA_PTS][KNN][4];     // 16 KB
    __shared__ float kf[64][OA_PTS];          // 8 KB
    int n0 = blockIdx.x * OA_PTS;
    int t  = threadIdx.x;  // 256
    float a = pr[0];
    for (int i = t; i < 128 * OA_PTS; i += 256) {
        int ch = i / OA_PTS, nn = i % OA_PTS;
        float x = g_hout[(size_t)ch * NPTS + n0 + nn];
        int gr = ch >> 4;
        x = (x - g_out_mu[gr]) * g_out_inv[gr] * gma[ch] + bta[ch];
        act[ch][nn] = (x >= 0.f) ? x : a * x;
    }
    for (int i = t; i < OA_PTS * KNN * 4; i += 256)
        ((float*)kin)[i] = g_kin[(size_t)n0 * KNN * 4 + i];
    __syncthreads();
    // knn features: GN+prelu+max over 32 nbrs for (pt, ch)
    {
        float ak = kpr[0];
        for (int i = t; i < 64 * OA_PTS; i += 256) {
            int ch = i / OA_PTS, nn = i % OA_PTS;
            float w0 = kw1[ch * 4 + 0], w1_ = kw1[ch * 4 + 1];
            float w2_ = kw1[ch * 4 + 2], w3_ = kw1[ch * 4 + 3];
            float bb = kb1[ch];
            float mu = g_knn_mu[ch >> 3], inv = g_knn_inv[ch >> 3];
            float gg = kgma[ch], bt_ = kbta[ch];
            float mx = -INFINITY;
#pragma unroll
            for (int s = 0; s < KNN; s++) {
                float h = w0 * kin[nn][s][0] + w1_ * kin[nn][s][1]
                        + w2_ * kin[nn][s][2] + w3_ * kin[nn][s][3] + bb;
                h = (h - mu) * inv * gg + bt_;
                h = (h >= 0.f) ? h : ak * h;
                mx = fmaxf(mx, h);
            }
            kf[ch][nn] = mx;
        }
    }
    __syncthreads();
    for (int i = t; i < 64 * OA_PTS; i += 256) {
        int o = i / OA_PTS, nn = i % OA_PTS;
        float acc = b2[o] + kob[o];
        for (int c = 0; c < 128; c++) acc += w2[o * 128 + c] * act[c][nn];
#pragma unroll
        for (int c = 0; c < 64; c++)  acc += kow[o * 64 + c] * kf[c][nn];
        out[(size_t)o * NPTS + n0 + nn] = acc;
    }
}

// ---------------- launch ----------------
extern "C" void kernel_launch(void* const* d_in, const int* in_sizes, int n_in,
                              void* d_out, int out_size) {
    const float* fmap1  = (const float*)d_in[0];
    const float* fmap2  = (const float*)d_in[1];
    const float* xyz2   = (const float*)d_in[2];
    const float* coords = (const float*)d_in[3];
    const float* out_w1 = (const float*)d_in[4];
    const float* out_b1 = (const float*)d_in[5];
    const float* out_g  = (const float*)d_in[6];
    const float* out_bt = (const float*)d_in[7];
    const float* out_pr = (const float*)d_in[8];
    const float* out_w2 = (const float*)d_in[9];
    const float* out_b2 = (const float*)d_in[10];
    const float* vox_w1 = (const float*)d_in[11];
    const float* vox_b1 = (const float*)d_in[12];
    const float* vox_g  = (const float*)d_in[13];
    const float* vox_bt = (const float*)d_in[14];
    const float* vox_pr = (const float*)d_in[15];
    const float* vox_w2 = (const float*)d_in[16];
    const float* vox_b2 = (const float*)d_in[17];
    const float* knn_w1 = (const float*)d_in[18];
    const float* knn_b1 = (const float*)d_in[19];
    const float* knn_g  = (const float*)d_in[20];
    const float* knn_bt = (const float*)d_in[21];
    const float* knn_pr = (const float*)d_in[22];
    const float* knn_ow = (const float*)d_in[23];
    const float* knn_ob = (const float*)d_in[24];
    float* out = (float*)d_out;

    cudaFuncSetAttribute(gemm_mma_kernel, cudaFuncAttributeMaxDynamicSharedMemorySize,
                         SM_GEMM_TOTAL);

    prep_kernel<<<dim3(NPTS / 64, 2), 256>>>(fmap1, fmap2);
    gemm_mma_kernel<<<dim3(NPTS / 128, NPTS / 128), 256, SM_GEMM_TOTAL>>>();
    topk_kernel<<<NPTS, 256>>>(xyz2);
    pointfeat_kernel<<<NPTS, 128>>>(coords, vox_w1, vox_b1, knn_w1, knn_b1);
    finalize_vk_kernel<<<1, 32>>>();
    vox_apply_kernel<<<(NPTS * 27 + 255) / 256, 256>>>(vox_w1, vox_b1, vox_g, vox_bt,
                                                       vox_pr, vox_w2, vox_b2);
    out_conv1_kernel<<<NPTS / 32, 128>>>(out_w1, out_b1);
    finalize_out_kernel<<<1, 32>>>();
    out_apply_kernel<<<NPTS / OA_PTS, 256>>>(out_g, out_bt, out_pr, out_w2, out_b2,
                                             knn_w1, knn_b1, knn_g, knn_bt, knn_pr,
                                             knn_ow, knn_ob, out);
}